// round 1
// baseline (speedup 1.0000x reference)
#include <cuda_runtime.h>
#include <cuda_bf16.h>
#include <math.h>

// Problem constants (fixed shapes per reference)
#define NN 4096
#define EE 256
#define KK 128
#define BB 64
#define DD 8

// ---------------- scratch (no allocations allowed) ----------------
__device__ float g_t0[NN * EE];
__device__ float g_t1[NN * EE];
__device__ float g_hres[NN * EE];
__device__ float g_hu[NN * EE];
__device__ float g_c[NN * KK];
__device__ float g_s[NN * KK];
__device__ float g_sfr[BB * KK * EE];
__device__ float g_sfi[BB * KK * EE];
__device__ float g_kf[KK * EE];
__device__ int   g_off[BB + 1];

// ---------------- helpers ----------------
__device__ __forceinline__ float silu(float v) {
    return v / (1.0f + __expf(-v));
}

// ---------------- segment offsets from sorted batch_seg ----------------
__global__ void seg_offsets_kernel(const int* __restrict__ seg) {
    int n = blockIdx.x * blockDim.x + threadIdx.x;
    if (n >= NN) return;
    int s = seg[n];
    if (n == 0) {
        for (int b = 0; b <= s; b++) g_off[b] = 0;
    } else {
        int p = seg[n - 1];
        for (int b = p + 1; b <= s; b++) g_off[b] = n;
    }
    if (n == NN - 1) {
        for (int b = s + 1; b <= BB; b++) g_off[b] = NN;
    }
}

// ---------------- dot products + cos/sin ----------------
// dot[n,k] = sum_d k[seg[n],k,d] * x[n,d]
__global__ void dot_kernel(const float* __restrict__ x,
                           const float* __restrict__ kvec,
                           const int* __restrict__ seg,
                           float* __restrict__ dot_out) {
    int n = blockIdx.x;
    int kk = threadIdx.x;  // 128
    int b = seg[n];
    float x0 = x[n * 3 + 0], x1 = x[n * 3 + 1], x2 = x[n * 3 + 2];
    const float* kr = kvec + ((size_t)b * KK + kk) * 3;
    float d = kr[0] * x0 + kr[1] * x1 + kr[2] * x2;
    dot_out[n * KK + kk] = d;
    float cv, sv;
    sincosf(d, &sv, &cv);
    g_c[n * KK + kk] = cv;
    g_s[n * KK + kk] = sv;
}

// ---------------- low-rank k-filter: kf[k,e] = sum_d Wup[e,d]*Wdn[d,k] ----------------
__global__ void kf_kernel(const float* __restrict__ Wup,
                          const float* __restrict__ Wdn) {
    int e = threadIdx.x;   // 256
    int k = blockIdx.x;    // 128
    float a = 0.f;
#pragma unroll
    for (int d = 0; d < DD; d++) a += Wup[e * DD + d] * Wdn[d * KK + k];
    g_kf[k * EE + e] = a;
}

// ---------------- structure factors (kfilter folded in) ----------------
// sfr[b,k,e] = kf[k,e] * sum_{n in b} c[n,k]*hres[n,e]   (and sfi with s)
__global__ void sf_kernel() {
    int b  = blockIdx.z;
    int k0 = blockIdx.y * 32;
    int e0 = blockIdx.x * 32;
    int tx = threadIdx.x;  // e
    int ty = threadIdx.y;  // k
    __shared__ float csh[32][33], ssh[32][33], hsh[32][33];
    int st = g_off[b], en = g_off[b + 1];
    float aR = 0.f, aI = 0.f;
    for (int n0 = st; n0 < en; n0 += 32) {
        int n = n0 + ty;
        bool v = (n < en);
        csh[ty][tx] = v ? g_c[n * KK + k0 + tx] : 0.f;
        ssh[ty][tx] = v ? g_s[n * KK + k0 + tx] : 0.f;
        hsh[ty][tx] = v ? g_hres[n * EE + e0 + tx] : 0.f;
        __syncthreads();
#pragma unroll
        for (int nn = 0; nn < 32; nn++) {
            float hv = hsh[nn][tx];
            aR += csh[nn][ty] * hv;
            aI += ssh[nn][ty] * hv;
        }
        __syncthreads();
    }
    float f = g_kf[(k0 + ty) * EE + e0 + tx];
    size_t idx = ((size_t)b * KK + k0 + ty) * EE + e0 + tx;
    g_sfr[idx] = aR * f;
    g_sfi[idx] = aI * f;
}

// ---------------- back-projection to atoms ----------------
// hu[n,e] = 0.01 * sum_k ( sfr[b,k,e]*c[n,k] + sfi[b,k,e]*s[n,k] )
__global__ void hupd_kernel(const int* __restrict__ seg) {
    int n0 = blockIdx.y * 32;
    int e0 = blockIdx.x * 32;
    int tx = threadIdx.x;  // e
    int ty = threadIdx.y;  // atom row
    int n = n0 + ty;
    int b = seg[n];
    __shared__ float csh[32][33], ssh[32][33];
    float acc = 0.f;
    for (int k0 = 0; k0 < KK; k0 += 32) {
        csh[ty][tx] = g_c[n * KK + k0 + tx];
        ssh[ty][tx] = g_s[n * KK + k0 + tx];
        __syncthreads();
        const float* pr = g_sfr + ((size_t)b * KK + k0) * EE + e0 + tx;
        const float* pi = g_sfi + ((size_t)b * KK + k0) * EE + e0 + tx;
#pragma unroll
        for (int kk = 0; kk < 32; kk++) {
            acc += csh[ty][kk] * pr[kk * EE] + ssh[ty][kk] * pi[kk * EE];
        }
        __syncthreads();
    }
    g_hu[n * EE + e0 + tx] = 0.01f * acc;
}

// ---------------- fused SGEMM: C = silu(A @ W^T) [+ skip] ----------------
// A: (NN, EE) row-major, W: (EE, EE) row-major (output-major), C: (NN, EE)
// 64x64 tile, BK=16, 256 threads, 4x4 register micro-tile
__global__ void gemm_nt_kernel(const float* __restrict__ A,
                               const float* __restrict__ W,
                               const float* __restrict__ skip,
                               float* __restrict__ C) {
    __shared__ float As[16][64];
    __shared__ float Ws[16][64];
    int m0 = blockIdx.y * 64;
    int n0 = blockIdx.x * 64;
    int t = threadIdx.x;       // 256
    int tx = t & 15;           // 0..15
    int ty = t >> 4;           // 0..15
    float acc[4][4] = {};
    for (int j0 = 0; j0 < EE; j0 += 16) {
#pragma unroll
        for (int l = 0; l < 4; l++) {
            int idx = t + 256 * l;
            int r = idx >> 4;
            int jj = idx & 15;
            As[jj][r] = A[(m0 + r) * EE + j0 + jj];
            Ws[jj][r] = W[(n0 + r) * EE + j0 + jj];
        }
        __syncthreads();
#pragma unroll
        for (int jj = 0; jj < 16; jj++) {
            float a[4], bb[4];
#pragma unroll
            for (int i = 0; i < 4; i++) a[i] = As[jj][ty * 4 + i];
#pragma unroll
            for (int i = 0; i < 4; i++) bb[i] = Ws[jj][tx * 4 + i];
#pragma unroll
            for (int i = 0; i < 4; i++)
#pragma unroll
                for (int q = 0; q < 4; q++) acc[i][q] += a[i] * bb[q];
        }
        __syncthreads();
    }
#pragma unroll
    for (int i = 0; i < 4; i++) {
        int m = m0 + ty * 4 + i;
#pragma unroll
        for (int q = 0; q < 4; q++) {
            int nn = n0 + tx * 4 + q;
            float v = acc[i][q];
            v = silu(v);
            if (skip) v += skip[m * EE + nn];
            C[m * EE + nn] = v;
        }
    }
}

// ---------------- launch ----------------
extern "C" void kernel_launch(void* const* d_in, const int* in_sizes, int n_in,
                              void* d_out, int out_size) {
    const float *h = nullptr, *x = nullptr, *kv = nullptr;
    const float *Wpre = nullptr, *Wdn = nullptr, *Wup = nullptr;
    const float *W0 = nullptr, *Wres = nullptr;
    const int* seg = nullptr;

    for (int i = 0; i < n_in; i++) {
        switch (in_sizes[i]) {
            case NN * EE:           h    = (const float*)d_in[i]; break;
            case NN * 3:            x    = (const float*)d_in[i]; break;
            case BB * KK * 3:       kv   = (const float*)d_in[i]; break;
            case NN:                seg  = (const int*)d_in[i];   break;
            case 2 * EE * EE:       Wpre = (const float*)d_in[i]; break;
            case DD * KK:           Wdn  = (const float*)d_in[i]; break;
            case EE * DD:           Wup  = (const float*)d_in[i]; break;
            case EE * EE:           W0   = (const float*)d_in[i]; break;
            case 3 * 2 * EE * EE:   Wres = (const float*)d_in[i]; break;
            default: break;  // num_batch scalar, ignored
        }
    }

    float* out = (float*)d_out;
    float* out_hu  = out;            // (NN, EE)
    float* out_dot = out + NN * EE;  // (NN, KK)

    // resolve scratch device addresses
    float *t0, *t1, *hres, *hu;
    cudaGetSymbolAddress((void**)&t0,   g_t0);
    cudaGetSymbolAddress((void**)&t1,   g_t1);
    cudaGetSymbolAddress((void**)&hres, g_hres);
    cudaGetSymbolAddress((void**)&hu,   g_hu);

    dim3 gemm_grid(EE / 64, NN / 64);
    const int gemm_threads = 256;

    // 1) pre-residual: hres = h + silu(silu(h @ Wpre0^T) @ Wpre1^T)
    gemm_nt_kernel<<<gemm_grid, gemm_threads>>>(h, Wpre, nullptr, t0);
    gemm_nt_kernel<<<gemm_grid, gemm_threads>>>(t0, Wpre + EE * EE, h, hres);

    // 2) segment offsets
    seg_offsets_kernel<<<(NN + 255) / 256, 256>>>(seg);

    // 3) dot + cos/sin (dot goes straight to output)
    dot_kernel<<<NN, KK>>>(x, kv, seg, out_dot);

    // 4) kfilter
    kf_kernel<<<KK, EE>>>(Wup, Wdn);

    // 5) structure factors (kfilter folded in)
    sf_kernel<<<dim3(EE / 32, KK / 32, BB), dim3(32, 32)>>>();

    // 6) back-projection (0.01 scale folded in)
    hupd_kernel<<<dim3(EE / 32, NN / 32), dim3(32, 32)>>>(seg);

    // 7) update MLP: hu = silu(h_update @ W0^T)
    gemm_nt_kernel<<<gemm_grid, gemm_threads>>>(hu, W0, nullptr, t0);

    // 8) 3 residual blocks; last one writes directly to d_out
    for (int i = 0; i < 3; i++) {
        const float* Wr0 = Wres + (size_t)i * 2 * EE * EE;
        const float* Wr1 = Wr0 + EE * EE;
        gemm_nt_kernel<<<gemm_grid, gemm_threads>>>(t0, Wr0, nullptr, t1);
        float* dst = (i == 2) ? out_hu : t0;
        gemm_nt_kernel<<<gemm_grid, gemm_threads>>>(t1, Wr1, t0, dst);
    }
}

// round 3
// speedup vs baseline: 1.7306x; 1.7306x over previous
#include <cuda_runtime.h>
#include <cuda_bf16.h>
#include <math.h>
#include <stdint.h>

// Problem constants (fixed shapes per reference)
#define NN 4096
#define EE 256
#define KK 128
#define BB 64
#define DD 8

// ---------------- scratch (no allocations allowed) ----------------
__device__ float g_t0[NN * EE];
__device__ float g_hres[NN * EE];
__device__ float g_c[NN * KK];
__device__ float g_s[NN * KK];
__device__ float g_sfr[BB * KK * EE];
__device__ float g_sfi[BB * KK * EE];
__device__ float g_kf[KK * EE];
__device__ int   g_off[BB + 1];
// bf16 hi/lo activation buffers: layout (NN, 512) = [hi(256) | lo(256)]
__device__ __nv_bfloat16 g_x2a[NN * 512];
__device__ __nv_bfloat16 g_x2b[NN * 512];
// concatenated weights: 9 matrices, each (256, 768) = [hi | lo | hi] along K
__device__ __nv_bfloat16 g_wc[9 * 256 * 768];

// ---------------- helpers ----------------
__device__ __forceinline__ float silu(float v) {
    return v / (1.0f + __expf(-v));
}

__device__ __forceinline__ uint32_t smem_u32(const void* p) {
    uint32_t a;
    asm("{ .reg .u64 t; cvta.to.shared.u64 t, %1; cvt.u32.u64 %0, t; }" : "=r"(a) : "l"(p));
    return a;
}

#define LDMATRIX_X4(r0, r1, r2, r3, addr) \
    asm volatile("ldmatrix.sync.aligned.m8n8.x4.shared.b16 {%0,%1,%2,%3}, [%4];" \
                 : "=r"(r0), "=r"(r1), "=r"(r2), "=r"(r3) : "r"(addr))

#define MMA_BF16(c, a, b0, b1) \
    asm volatile("mma.sync.aligned.m16n8k16.row.col.f32.bf16.bf16.f32 " \
                 "{%0,%1,%2,%3},{%4,%5,%6,%7},{%8,%9},{%0,%1,%2,%3};" \
                 : "+f"((c)[0]), "+f"((c)[1]), "+f"((c)[2]), "+f"((c)[3]) \
                 : "r"((a)[0]), "r"((a)[1]), "r"((a)[2]), "r"((a)[3]), \
                   "r"(b0), "r"(b1))

// ============================================================================
// HMMA GEMM: out = silu(A @ W^T) [+ skip]
// A2: (NN, 512) bf16 [hi|lo].  Wc: (256, 768) bf16 [hi|lo|hi].
// 3-term split via K=768: Ahi*Whi (k 0-255), Ahi*Wlo (256-511), Alo*Whi (512-767).
// A column for global k: k<256 ? k : k-256.
// CTA tile 128x64, 8 warps (4x2), warp tile 32x32, BK=32, double-buffered smem.
// ============================================================================
#define ASTRIDE 40  // bf16 per smem row (80B) — conflict-free for ldmatrix

__global__ void __launch_bounds__(256, 1) gemm_mma_kernel(
    const __nv_bfloat16* __restrict__ A2,
    const __nv_bfloat16* __restrict__ Wc,
    const float* __restrict__ skip,
    float* __restrict__ outf,
    __nv_bfloat16* __restrict__ out2)
{
    __shared__ __align__(16) __nv_bfloat16 As[2][128 * ASTRIDE];
    __shared__ __align__(16) __nv_bfloat16 Bs[2][64 * ASTRIDE];

    int tid = threadIdx.x, wid = tid >> 5, lane = tid & 31;
    int m0 = blockIdx.y * 128, n0 = blockIdx.x * 64;
    int warp_m = (wid >> 1) * 32, warp_n = (wid & 1) * 32;

    float acc[2][4][4];
#pragma unroll
    for (int i = 0; i < 2; i++)
#pragma unroll
        for (int j = 0; j < 4; j++)
#pragma unroll
            for (int q = 0; q < 4; q++) acc[i][j][q] = 0.f;

    const uint4* gA = reinterpret_cast<const uint4*>(A2);
    const uint4* gW = reinterpret_cast<const uint4*>(Wc);
    int rL = tid >> 2;        // 0..63
    int cL = tid & 3;         // 0..3 (16B groups within 32-col chunk)

    uint4 pa0, pa1, pb;

    // prologue: load chunk 0
    {
        int k = 0, acol = 0;
        pa0 = gA[(size_t)(m0 + rL) * 64 + (acol >> 3) + cL];
        pa1 = gA[(size_t)(m0 + rL + 64) * 64 + (acol >> 3) + cL];
        pb  = gW[(size_t)(n0 + rL) * 96 + (k >> 3) + cL];
        *reinterpret_cast<uint4*>(&As[0][rL * ASTRIDE + cL * 8]) = pa0;
        *reinterpret_cast<uint4*>(&As[0][(rL + 64) * ASTRIDE + cL * 8]) = pa1;
        *reinterpret_cast<uint4*>(&Bs[0][rL * ASTRIDE + cL * 8]) = pb;
    }
    __syncthreads();

#pragma unroll 1
    for (int ch = 0; ch < 24; ch++) {
        int s = ch & 1;
        bool more = (ch < 23);
        if (more) {
            int k = (ch + 1) * 32;
            int acol = (k >= 256) ? (k - 256) : k;
            pa0 = gA[(size_t)(m0 + rL) * 64 + (acol >> 3) + cL];
            pa1 = gA[(size_t)(m0 + rL + 64) * 64 + (acol >> 3) + cL];
            pb  = gW[(size_t)(n0 + rL) * 96 + (k >> 3) + cL];
        }

        uint32_t aBase = smem_u32(&As[s][0]);
        uint32_t bBase = smem_u32(&Bs[s][0]);
#pragma unroll
        for (int kh = 0; kh < 2; kh++) {
            uint32_t a[2][4], b[2][4];
#pragma unroll
            for (int mt = 0; mt < 2; mt++) {
                int row = warp_m + mt * 16 + (lane & 15);
                uint32_t addr = aBase + row * (ASTRIDE * 2) + kh * 32 + (lane >> 4) * 16;
                LDMATRIX_X4(a[mt][0], a[mt][1], a[mt][2], a[mt][3], addr);
            }
#pragma unroll
            for (int nt = 0; nt < 2; nt++) {
                int row = warp_n + nt * 16 + (lane & 15);
                uint32_t addr = bBase + row * (ASTRIDE * 2) + kh * 32 + (lane >> 4) * 16;
                LDMATRIX_X4(b[nt][0], b[nt][1], b[nt][2], b[nt][3], addr);
            }
#pragma unroll
            for (int mt = 0; mt < 2; mt++)
#pragma unroll
                for (int j = 0; j < 4; j++) {
                    int nt = j >> 1, sel = j & 1;
                    MMA_BF16(acc[mt][j], a[mt], b[nt][sel], b[nt][sel + 2]);
                }
        }

        if (more) {
            int d = s ^ 1;
            *reinterpret_cast<uint4*>(&As[d][rL * ASTRIDE + cL * 8]) = pa0;
            *reinterpret_cast<uint4*>(&As[d][(rL + 64) * ASTRIDE + cL * 8]) = pa1;
            *reinterpret_cast<uint4*>(&Bs[d][rL * ASTRIDE + cL * 8]) = pb;
        }
        __syncthreads();
    }

    // ---------------- epilogue ----------------
    int r0 = lane >> 2, cp = (lane & 3) * 2;
#pragma unroll
    for (int mt = 0; mt < 2; mt++) {
#pragma unroll
        for (int j = 0; j < 4; j++) {
            int n = n0 + warp_n + j * 8 + cp;
#pragma unroll
            for (int half = 0; half < 2; half++) {
                int m = m0 + warp_m + mt * 16 + r0 + half * 8;
                float v0 = acc[mt][j][half * 2 + 0];
                float v1 = acc[mt][j][half * 2 + 1];
                v0 = silu(v0);
                v1 = silu(v1);
                if (skip) {
                    float2 sk = *reinterpret_cast<const float2*>(skip + (size_t)m * 256 + n);
                    v0 += sk.x; v1 += sk.y;
                }
                if (outf) {
                    float2 o; o.x = v0; o.y = v1;
                    *reinterpret_cast<float2*>(outf + (size_t)m * 256 + n) = o;
                }
                if (out2) {
                    __nv_bfloat16 h0 = __float2bfloat16(v0);
                    __nv_bfloat16 h1 = __float2bfloat16(v1);
                    __nv_bfloat162 hh; hh.x = h0; hh.y = h1;
                    __nv_bfloat162 ll;
                    ll.x = __float2bfloat16(v0 - __bfloat162float(h0));
                    ll.y = __float2bfloat16(v1 - __bfloat162float(h1));
                    *reinterpret_cast<__nv_bfloat162*>(out2 + (size_t)m * 512 + n) = hh;
                    *reinterpret_cast<__nv_bfloat162*>(out2 + (size_t)m * 512 + 256 + n) = ll;
                }
            }
        }
    }
}

// ---------------- hi/lo conversion of h ----------------
__global__ void conv_h_kernel(const float* __restrict__ h) {
    int idx = blockIdx.x * 256 + threadIdx.x;
    int m = idx >> 8, e = idx & 255;
    float v = h[idx];
    __nv_bfloat16 hi = __float2bfloat16(v);
    g_x2a[(size_t)m * 512 + e] = hi;
    g_x2a[(size_t)m * 512 + 256 + e] = __float2bfloat16(v - __bfloat162float(hi));
}

// ---------------- weight concat conversion: 9 x (256, 768) [hi|lo|hi] --------
__global__ void conv_w_kernel(const float* __restrict__ Wpre,
                              const float* __restrict__ W0,
                              const float* __restrict__ Wres) {
    int g = blockIdx.y;
    int i = blockIdx.x * 256 + threadIdx.x;  // 0..65535
    int n = i >> 8, k = i & 255;
    const float* src = (g < 2) ? (Wpre + (size_t)g * 65536)
                     : (g == 2) ? W0
                     : (Wres + (size_t)(g - 3) * 65536);
    float v = src[i];
    __nv_bfloat16 hi = __float2bfloat16(v);
    __nv_bfloat16 lo = __float2bfloat16(v - __bfloat162float(hi));
    __nv_bfloat16* dst = g_wc + (size_t)g * 256 * 768 + (size_t)n * 768;
    dst[k] = hi;
    dst[256 + k] = lo;
    dst[512 + k] = hi;
}

// ---------------- segment offsets from sorted batch_seg ----------------
__global__ void seg_offsets_kernel(const int* __restrict__ seg) {
    int n = blockIdx.x * blockDim.x + threadIdx.x;
    if (n >= NN) return;
    int s = seg[n];
    if (n == 0) {
        for (int b = 0; b <= s; b++) g_off[b] = 0;
    } else {
        int p = seg[n - 1];
        for (int b = p + 1; b <= s; b++) g_off[b] = n;
    }
    if (n == NN - 1) {
        for (int b = s + 1; b <= BB; b++) g_off[b] = NN;
    }
}

// ---------------- dot products + cos/sin ----------------
__global__ void dot_kernel(const float* __restrict__ x,
                           const float* __restrict__ kvec,
                           const int* __restrict__ seg,
                           float* __restrict__ dot_out) {
    int n = blockIdx.x;
    int kk = threadIdx.x;  // 128
    int b = seg[n];
    float x0 = x[n * 3 + 0], x1 = x[n * 3 + 1], x2 = x[n * 3 + 2];
    const float* kr = kvec + ((size_t)b * KK + kk) * 3;
    float d = kr[0] * x0 + kr[1] * x1 + kr[2] * x2;
    dot_out[n * KK + kk] = d;
    float cv, sv;
    sincosf(d, &sv, &cv);
    g_c[n * KK + kk] = cv;
    g_s[n * KK + kk] = sv;
}

// ---------------- low-rank k-filter ----------------
__global__ void kf_kernel(const float* __restrict__ Wup,
                          const float* __restrict__ Wdn) {
    int e = threadIdx.x;
    int k = blockIdx.x;
    float a = 0.f;
#pragma unroll
    for (int d = 0; d < DD; d++) a += Wup[e * DD + d] * Wdn[d * KK + k];
    g_kf[k * EE + e] = a;
}

// ---------------- structure factors (kfilter folded in) ----------------
__global__ void sf_kernel() {
    int b  = blockIdx.z;
    int k0 = blockIdx.y * 32;
    int e0 = blockIdx.x * 32;
    int tx = threadIdx.x;
    int ty = threadIdx.y;
    __shared__ float csh[32][33], ssh[32][33], hsh[32][33];
    int st = g_off[b], en = g_off[b + 1];
    float aR = 0.f, aI = 0.f;
    for (int n0 = st; n0 < en; n0 += 32) {
        int n = n0 + ty;
        bool v = (n < en);
        csh[ty][tx] = v ? g_c[n * KK + k0 + tx] : 0.f;
        ssh[ty][tx] = v ? g_s[n * KK + k0 + tx] : 0.f;
        hsh[ty][tx] = v ? g_hres[n * EE + e0 + tx] : 0.f;
        __syncthreads();
#pragma unroll
        for (int nn = 0; nn < 32; nn++) {
            float hv = hsh[nn][tx];
            aR += csh[nn][ty] * hv;
            aI += ssh[nn][ty] * hv;
        }
        __syncthreads();
    }
    float f = g_kf[(k0 + ty) * EE + e0 + tx];
    size_t idx = ((size_t)b * KK + k0 + ty) * EE + e0 + tx;
    g_sfr[idx] = aR * f;
    g_sfi[idx] = aI * f;
}

// ---------------- back-projection; writes hi/lo bf16 of 0.01*acc ------------
__global__ void hupd_kernel(const int* __restrict__ seg) {
    int n0 = blockIdx.y * 32;
    int e0 = blockIdx.x * 32;
    int tx = threadIdx.x;
    int ty = threadIdx.y;
    int n = n0 + ty;
    int b = seg[n];
    __shared__ float csh[32][33], ssh[32][33];
    float acc = 0.f;
    for (int k0 = 0; k0 < KK; k0 += 32) {
        csh[ty][tx] = g_c[n * KK + k0 + tx];
        ssh[ty][tx] = g_s[n * KK + k0 + tx];
        __syncthreads();
        const float* pr = g_sfr + ((size_t)b * KK + k0) * EE + e0 + tx;
        const float* pi = g_sfi + ((size_t)b * KK + k0) * EE + e0 + tx;
#pragma unroll
        for (int kk = 0; kk < 32; kk++) {
            acc += csh[ty][kk] * pr[kk * EE] + ssh[ty][kk] * pi[kk * EE];
        }
        __syncthreads();
    }
    float v = 0.01f * acc;
    __nv_bfloat16 hi = __float2bfloat16(v);
    g_x2a[(size_t)n * 512 + e0 + tx] = hi;
    g_x2a[(size_t)n * 512 + 256 + e0 + tx] = __float2bfloat16(v - __bfloat162float(hi));
}

// ---------------- launch ----------------
extern "C" void kernel_launch(void* const* d_in, const int* in_sizes, int n_in,
                              void* d_out, int out_size) {
    const float *h = nullptr, *x = nullptr, *kv = nullptr;
    const float *Wpre = nullptr, *Wdn = nullptr, *Wup = nullptr;
    const float *W0 = nullptr, *Wres = nullptr;
    const int* seg = nullptr;

    for (int i = 0; i < n_in; i++) {
        switch (in_sizes[i]) {
            case NN * EE:           h    = (const float*)d_in[i]; break;
            case NN * 3:            x    = (const float*)d_in[i]; break;
            case BB * KK * 3:       kv   = (const float*)d_in[i]; break;
            case NN:                seg  = (const int*)d_in[i];   break;
            case 2 * EE * EE:       Wpre = (const float*)d_in[i]; break;
            case DD * KK:           Wdn  = (const float*)d_in[i]; break;
            case EE * DD:           Wup  = (const float*)d_in[i]; break;
            case EE * EE:           W0   = (const float*)d_in[i]; break;
            case 3 * 2 * EE * EE:   Wres = (const float*)d_in[i]; break;
            default: break;
        }
    }

    float* out = (float*)d_out;
    float* out_hu  = out;            // (NN, EE)
    float* out_dot = out + NN * EE;  // (NN, KK)

    float *t0, *hres;
    __nv_bfloat16 *x2a, *x2b, *wc;
    cudaGetSymbolAddress((void**)&t0,   g_t0);
    cudaGetSymbolAddress((void**)&hres, g_hres);
    cudaGetSymbolAddress((void**)&x2a,  g_x2a);
    cudaGetSymbolAddress((void**)&x2b,  g_x2b);
    cudaGetSymbolAddress((void**)&wc,   g_wc);

    dim3 ggrid(EE / 64, NN / 128);  // (4, 32) = 128 CTAs

    // conversions
    conv_w_kernel<<<dim3(256, 9), 256>>>(Wpre, W0, Wres);
    conv_h_kernel<<<NN * EE / 256, 256>>>(h);

    // pre-residual: x2b = silu(h@W0'), hres = h + silu(x2b@W1')
    gemm_mma_kernel<<<ggrid, 256>>>(x2a, wc + 0 * 256 * 768, nullptr, nullptr, x2b);
    gemm_mma_kernel<<<ggrid, 256>>>(x2b, wc + 1 * 256 * 768, h, hres, nullptr);

    // Ewald geometry path
    seg_offsets_kernel<<<(NN + 255) / 256, 256>>>(seg);
    dot_kernel<<<NN, KK>>>(x, kv, seg, out_dot);
    kf_kernel<<<KK, EE>>>(Wup, Wdn);
    sf_kernel<<<dim3(EE / 32, KK / 32, BB), dim3(32, 32)>>>();
    hupd_kernel<<<dim3(EE / 32, NN / 32), dim3(32, 32)>>>(seg);  // -> g_x2a (hi/lo)

    // update MLP: t0 = silu(hu @ W0^T) (fp32 copy needed as residual skip)
    gemm_mma_kernel<<<ggrid, 256>>>(x2a, wc + 2 * 256 * 768, nullptr, t0, x2b);

    // 3 residual blocks
    for (int i = 0; i < 3; i++) {
        const __nv_bfloat16* wa = wc + (size_t)(3 + 2 * i) * 256 * 768;
        const __nv_bfloat16* wb = wc + (size_t)(4 + 2 * i) * 256 * 768;
        gemm_mma_kernel<<<ggrid, 256>>>(x2b, wa, nullptr, nullptr, x2a);
        float* dstf = (i == 2) ? out_hu : t0;
        __nv_bfloat16* dst2 = (i == 2) ? nullptr : x2b;
        gemm_mma_kernel<<<ggrid, 256>>>(x2a, wb, t0, dstf, dst2);
    }
}

// round 4
// speedup vs baseline: 1.8747x; 1.0833x over previous
#include <cuda_runtime.h>
#include <cuda_bf16.h>
#include <math.h>
#include <stdint.h>

// Problem constants (fixed shapes per reference)
#define NN 4096
#define EE 256
#define KK 128
#define BB 64
#define DD 8

// ---------------- scratch (no allocations allowed) ----------------
__device__ float g_t0[NN * EE];
__device__ float g_hres[NN * EE];
__device__ float g_c[NN * KK];
__device__ float g_s[NN * KK];
__device__ float g_sfr[BB * KK * EE];
__device__ float g_sfi[BB * KK * EE];
__device__ float g_kf[KK * EE];
__device__ int   g_off[BB + 1];
// bf16 hi/lo activation buffers: layout (NN, 512) = [hi(256) | lo(256)]
__device__ __nv_bfloat16 g_x2a[NN * 512];
__device__ __nv_bfloat16 g_x2b[NN * 512];
// concatenated weights: 9 matrices, each (256, 768) = [hi | lo | hi] along K
__device__ __nv_bfloat16 g_wc[9 * 256 * 768];

// ---------------- helpers ----------------
__device__ __forceinline__ float silu(float v) {
    return v / (1.0f + __expf(-v));
}

__device__ __forceinline__ uint32_t smem_u32(const void* p) {
    uint32_t a;
    asm("{ .reg .u64 t; cvta.to.shared.u64 t, %1; cvt.u32.u64 %0, t; }" : "=r"(a) : "l"(p));
    return a;
}

#define LDMATRIX_X4(r0, r1, r2, r3, addr) \
    asm volatile("ldmatrix.sync.aligned.m8n8.x4.shared.b16 {%0,%1,%2,%3}, [%4];" \
                 : "=r"(r0), "=r"(r1), "=r"(r2), "=r"(r3) : "r"(addr))

#define MMA_BF16(c, a, b0, b1) \
    asm volatile("mma.sync.aligned.m16n8k16.row.col.f32.bf16.bf16.f32 " \
                 "{%0,%1,%2,%3},{%4,%5,%6,%7},{%8,%9},{%0,%1,%2,%3};" \
                 : "+f"((c)[0]), "+f"((c)[1]), "+f"((c)[2]), "+f"((c)[3]) \
                 : "r"((a)[0]), "r"((a)[1]), "r"((a)[2]), "r"((a)[3]), \
                   "r"(b0), "r"(b1))

#define CP_ASYNC16(dst, src) \
    asm volatile("cp.async.cg.shared.global [%0], [%1], 16;" :: "r"(dst), "l"(src))
#define CP_COMMIT() asm volatile("cp.async.commit_group;" ::: "memory")

// ============================================================================
// HMMA GEMM: out = silu(A @ W^T) [+ skip]
// A2: (NN, 512) bf16 [hi|lo].  Wc: (256, 768) bf16 [hi|lo|hi].
// 3-term split via K=768: Ahi*Whi (k 0-255), Ahi*Wlo (256-511), Alo*Whi (512-767).
// CTA tile 128x64, 8 warps (4x2), warp tile 32x32, BK=64,
// 3-stage cp.async pipeline, smem row stride 144B (ldmatrix conflict-free).
// ============================================================================
#define BKB   128                 // bytes of K per chunk (64 bf16)
#define RSTR  144                 // smem row stride bytes
#define A_BYTES (128 * RSTR)      // 18432
#define B_BYTES (64 * RSTR)       // 9216
#define STG   (A_BYTES + B_BYTES) // 27648
#define GEMM_SMEM (3 * STG)       // 82944

__device__ __forceinline__ void load_chunk(
    uint32_t sb, int stage, int ch,
    const __nv_bfloat16* __restrict__ gA,
    const __nv_bfloat16* __restrict__ gW, int tid)
{
    int k = ch * 64;
    int acol = (k >= 256) ? (k - 256) : k;
    uint32_t base = sb + stage * STG;
#pragma unroll
    for (int l = 0; l < 4; l++) {
        int idx = tid + 256 * l;
        int r = idx >> 3, c = idx & 7;
        CP_ASYNC16(base + r * RSTR + c * 16,
                   gA + (size_t)r * 512 + acol + c * 8);
    }
#pragma unroll
    for (int l = 0; l < 2; l++) {
        int idx = tid + 256 * l;
        int r = idx >> 3, c = idx & 7;
        CP_ASYNC16(base + A_BYTES + r * RSTR + c * 16,
                   gW + (size_t)r * 768 + k + c * 8);
    }
    CP_COMMIT();
}

__global__ void __launch_bounds__(256, 1) gemm_mma_kernel(
    const __nv_bfloat16* __restrict__ A2,
    const __nv_bfloat16* __restrict__ Wc,
    const float* __restrict__ skip,
    float* __restrict__ outf,
    __nv_bfloat16* __restrict__ out2)
{
    extern __shared__ char smem[];
    uint32_t sb = smem_u32(smem);

    int tid = threadIdx.x, wid = tid >> 5, lane = tid & 31;
    int m0 = blockIdx.y * 128, n0 = blockIdx.x * 64;
    int warp_m = (wid >> 1) * 32, warp_n = (wid & 1) * 32;

    const __nv_bfloat16* gA = A2 + (size_t)m0 * 512;
    const __nv_bfloat16* gW = Wc + (size_t)n0 * 768;

    float acc[2][4][4];
#pragma unroll
    for (int i = 0; i < 2; i++)
#pragma unroll
        for (int j = 0; j < 4; j++)
#pragma unroll
            for (int q = 0; q < 4; q++) acc[i][j][q] = 0.f;

    // prologue: stages 0,1 in flight
    load_chunk(sb, 0, 0, gA, gW, tid);
    load_chunk(sb, 1, 1, gA, gW, tid);

    int stage = 0;
#pragma unroll 1
    for (int ch = 0; ch < 12; ch++) {
        if (ch < 11) asm volatile("cp.async.wait_group 1;" ::: "memory");
        else         asm volatile("cp.async.wait_group 0;" ::: "memory");
        __syncthreads();  // group ch visible to all; prev stage fully consumed

        if (ch + 2 < 12) {
            int ns = stage + 2; if (ns >= 3) ns -= 3;
            load_chunk(sb, ns, ch + 2, gA, gW, tid);
        }

        uint32_t aB = sb + stage * STG;
        uint32_t bB = aB + A_BYTES;
#pragma unroll
        for (int kh = 0; kh < 4; kh++) {
            uint32_t a[2][4], b[2][4];
#pragma unroll
            for (int mt = 0; mt < 2; mt++) {
                int row = warp_m + mt * 16 + (lane & 15);
                uint32_t addr = aB + row * RSTR + kh * 32 + (lane >> 4) * 16;
                LDMATRIX_X4(a[mt][0], a[mt][1], a[mt][2], a[mt][3], addr);
            }
#pragma unroll
            for (int nt = 0; nt < 2; nt++) {
                int row = warp_n + nt * 16 + (lane & 15);
                uint32_t addr = bB + row * RSTR + kh * 32 + (lane >> 4) * 16;
                LDMATRIX_X4(b[nt][0], b[nt][1], b[nt][2], b[nt][3], addr);
            }
#pragma unroll
            for (int mt = 0; mt < 2; mt++)
#pragma unroll
                for (int j = 0; j < 4; j++) {
                    int nt = j >> 1, sel = j & 1;
                    MMA_BF16(acc[mt][j], a[mt], b[nt][sel], b[nt][sel + 2]);
                }
        }

        stage++; if (stage >= 3) stage = 0;
    }

    // ---------------- epilogue ----------------
    int r0 = lane >> 2, cp = (lane & 3) * 2;
#pragma unroll
    for (int mt = 0; mt < 2; mt++) {
#pragma unroll
        for (int j = 0; j < 4; j++) {
            int n = n0 + warp_n + j * 8 + cp;
#pragma unroll
            for (int half = 0; half < 2; half++) {
                int m = m0 + warp_m + mt * 16 + r0 + half * 8;
                float v0 = acc[mt][j][half * 2 + 0];
                float v1 = acc[mt][j][half * 2 + 1];
                v0 = silu(v0);
                v1 = silu(v1);
                if (skip) {
                    float2 sk = *reinterpret_cast<const float2*>(skip + (size_t)m * 256 + n);
                    v0 += sk.x; v1 += sk.y;
                }
                if (outf) {
                    float2 o; o.x = v0; o.y = v1;
                    *reinterpret_cast<float2*>(outf + (size_t)m * 256 + n) = o;
                }
                if (out2) {
                    __nv_bfloat16 h0 = __float2bfloat16(v0);
                    __nv_bfloat16 h1 = __float2bfloat16(v1);
                    __nv_bfloat162 hh; hh.x = h0; hh.y = h1;
                    __nv_bfloat162 ll;
                    ll.x = __float2bfloat16(v0 - __bfloat162float(h0));
                    ll.y = __float2bfloat16(v1 - __bfloat162float(h1));
                    *reinterpret_cast<__nv_bfloat162*>(out2 + (size_t)m * 512 + n) = hh;
                    *reinterpret_cast<__nv_bfloat162*>(out2 + (size_t)m * 512 + 256 + n) = ll;
                }
            }
        }
    }
}

// ---------------- hi/lo conversion of h ----------------
__global__ void conv_h_kernel(const float* __restrict__ h) {
    int idx = blockIdx.x * 256 + threadIdx.x;
    int m = idx >> 8, e = idx & 255;
    float v = h[idx];
    __nv_bfloat16 hi = __float2bfloat16(v);
    g_x2a[(size_t)m * 512 + e] = hi;
    g_x2a[(size_t)m * 512 + 256 + e] = __float2bfloat16(v - __bfloat162float(hi));
}

// ---------------- weight concat conversion: 9 x (256, 768) [hi|lo|hi] --------
__global__ void conv_w_kernel(const float* __restrict__ Wpre,
                              const float* __restrict__ W0,
                              const float* __restrict__ Wres) {
    int g = blockIdx.y;
    int i = blockIdx.x * 256 + threadIdx.x;  // 0..65535
    int n = i >> 8, k = i & 255;
    const float* src = (g < 2) ? (Wpre + (size_t)g * 65536)
                     : (g == 2) ? W0
                     : (Wres + (size_t)(g - 3) * 65536);
    float v = src[i];
    __nv_bfloat16 hi = __float2bfloat16(v);
    __nv_bfloat16 lo = __float2bfloat16(v - __bfloat162float(hi));
    __nv_bfloat16* dst = g_wc + (size_t)g * 256 * 768 + (size_t)n * 768;
    dst[k] = hi;
    dst[256 + k] = lo;
    dst[512 + k] = hi;
}

// ---------------- segment offsets from sorted batch_seg ----------------
__global__ void seg_offsets_kernel(const int* __restrict__ seg) {
    int n = blockIdx.x * blockDim.x + threadIdx.x;
    if (n >= NN) return;
    int s = seg[n];
    if (n == 0) {
        for (int b = 0; b <= s; b++) g_off[b] = 0;
    } else {
        int p = seg[n - 1];
        for (int b = p + 1; b <= s; b++) g_off[b] = n;
    }
    if (n == NN - 1) {
        for (int b = s + 1; b <= BB; b++) g_off[b] = NN;
    }
}

// ---------------- dot products + cos/sin ----------------
__global__ void dot_kernel(const float* __restrict__ x,
                           const float* __restrict__ kvec,
                           const int* __restrict__ seg,
                           float* __restrict__ dot_out) {
    int n = blockIdx.x;
    int kk = threadIdx.x;  // 128
    int b = seg[n];
    float x0 = x[n * 3 + 0], x1 = x[n * 3 + 1], x2 = x[n * 3 + 2];
    const float* kr = kvec + ((size_t)b * KK + kk) * 3;
    float d = kr[0] * x0 + kr[1] * x1 + kr[2] * x2;
    dot_out[n * KK + kk] = d;
    float cv, sv;
    sincosf(d, &sv, &cv);
    g_c[n * KK + kk] = cv;
    g_s[n * KK + kk] = sv;
}

// ---------------- low-rank k-filter ----------------
__global__ void kf_kernel(const float* __restrict__ Wup,
                          const float* __restrict__ Wdn) {
    int e = threadIdx.x;
    int k = blockIdx.x;
    float a = 0.f;
#pragma unroll
    for (int d = 0; d < DD; d++) a += Wup[e * DD + d] * Wdn[d * KK + k];
    g_kf[k * EE + e] = a;
}

// ---------------- structure factors (kfilter folded in) ----------------
__global__ void sf_kernel() {
    int b  = blockIdx.z;
    int k0 = blockIdx.y * 32;
    int e0 = blockIdx.x * 32;
    int tx = threadIdx.x;
    int ty = threadIdx.y;
    __shared__ float csh[32][33], ssh[32][33], hsh[32][33];
    int st = g_off[b], en = g_off[b + 1];
    float aR = 0.f, aI = 0.f;
    for (int n0 = st; n0 < en; n0 += 32) {
        int n = n0 + ty;
        bool v = (n < en);
        csh[ty][tx] = v ? g_c[n * KK + k0 + tx] : 0.f;
        ssh[ty][tx] = v ? g_s[n * KK + k0 + tx] : 0.f;
        hsh[ty][tx] = v ? g_hres[n * EE + e0 + tx] : 0.f;
        __syncthreads();
#pragma unroll
        for (int nn = 0; nn < 32; nn++) {
            float hv = hsh[nn][tx];
            aR += csh[nn][ty] * hv;
            aI += ssh[nn][ty] * hv;
        }
        __syncthreads();
    }
    float f = g_kf[(k0 + ty) * EE + e0 + tx];
    size_t idx = ((size_t)b * KK + k0 + ty) * EE + e0 + tx;
    g_sfr[idx] = aR * f;
    g_sfi[idx] = aI * f;
}

// ---------------- back-projection; writes hi/lo bf16 of 0.01*acc ------------
__global__ void hupd_kernel(const int* __restrict__ seg) {
    int n0 = blockIdx.y * 32;
    int e0 = blockIdx.x * 32;
    int tx = threadIdx.x;
    int ty = threadIdx.y;
    int n = n0 + ty;
    int b = seg[n];
    __shared__ float csh[32][33], ssh[32][33];
    float acc = 0.f;
    for (int k0 = 0; k0 < KK; k0 += 32) {
        csh[ty][tx] = g_c[n * KK + k0 + tx];
        ssh[ty][tx] = g_s[n * KK + k0 + tx];
        __syncthreads();
        const float* pr = g_sfr + ((size_t)b * KK + k0) * EE + e0 + tx;
        const float* pi = g_sfi + ((size_t)b * KK + k0) * EE + e0 + tx;
#pragma unroll
        for (int kk = 0; kk < 32; kk++) {
            acc += csh[ty][kk] * pr[kk * EE] + ssh[ty][kk] * pi[kk * EE];
        }
        __syncthreads();
    }
    float v = 0.01f * acc;
    __nv_bfloat16 hi = __float2bfloat16(v);
    g_x2a[(size_t)n * 512 + e0 + tx] = hi;
    g_x2a[(size_t)n * 512 + 256 + e0 + tx] = __float2bfloat16(v - __bfloat162float(hi));
}

// ---------------- launch ----------------
extern "C" void kernel_launch(void* const* d_in, const int* in_sizes, int n_in,
                              void* d_out, int out_size) {
    const float *h = nullptr, *x = nullptr, *kv = nullptr;
    const float *Wpre = nullptr, *Wdn = nullptr, *Wup = nullptr;
    const float *W0 = nullptr, *Wres = nullptr;
    const int* seg = nullptr;

    for (int i = 0; i < n_in; i++) {
        switch (in_sizes[i]) {
            case NN * EE:           h    = (const float*)d_in[i]; break;
            case NN * 3:            x    = (const float*)d_in[i]; break;
            case BB * KK * 3:       kv   = (const float*)d_in[i]; break;
            case NN:                seg  = (const int*)d_in[i];   break;
            case 2 * EE * EE:       Wpre = (const float*)d_in[i]; break;
            case DD * KK:           Wdn  = (const float*)d_in[i]; break;
            case EE * DD:           Wup  = (const float*)d_in[i]; break;
            case EE * EE:           W0   = (const float*)d_in[i]; break;
            case 3 * 2 * EE * EE:   Wres = (const float*)d_in[i]; break;
            default: break;
        }
    }

    float* out = (float*)d_out;
    float* out_hu  = out;            // (NN, EE)
    float* out_dot = out + NN * EE;  // (NN, KK)

    float *t0, *hres;
    __nv_bfloat16 *x2a, *x2b, *wc;
    cudaGetSymbolAddress((void**)&t0,   g_t0);
    cudaGetSymbolAddress((void**)&hres, g_hres);
    cudaGetSymbolAddress((void**)&x2a,  g_x2a);
    cudaGetSymbolAddress((void**)&x2b,  g_x2b);
    cudaGetSymbolAddress((void**)&wc,   g_wc);

    cudaFuncSetAttribute(gemm_mma_kernel,
                         cudaFuncAttributeMaxDynamicSharedMemorySize, GEMM_SMEM);
    dim3 ggrid(EE / 64, NN / 128);  // (4, 32) = 128 CTAs

    // conversions
    conv_w_kernel<<<dim3(256, 9), 256>>>(Wpre, W0, Wres);
    conv_h_kernel<<<NN * EE / 256, 256>>>(h);

    // pre-residual: x2b = silu(h@W0'), hres = h + silu(x2b@W1')
    gemm_mma_kernel<<<ggrid, 256, GEMM_SMEM>>>(x2a, wc + 0 * 256 * 768, nullptr, nullptr, x2b);
    gemm_mma_kernel<<<ggrid, 256, GEMM_SMEM>>>(x2b, wc + 1 * 256 * 768, h, hres, nullptr);

    // Ewald geometry path
    seg_offsets_kernel<<<(NN + 255) / 256, 256>>>(seg);
    dot_kernel<<<NN, KK>>>(x, kv, seg, out_dot);
    kf_kernel<<<KK, EE>>>(Wup, Wdn);
    sf_kernel<<<dim3(EE / 32, KK / 32, BB), dim3(32, 32)>>>();
    hupd_kernel<<<dim3(EE / 32, NN / 32), dim3(32, 32)>>>(seg);  // -> g_x2a (hi/lo)

    // update MLP: t0 = silu(hu @ W0^T) (fp32 copy needed as residual skip)
    gemm_mma_kernel<<<ggrid, 256, GEMM_SMEM>>>(x2a, wc + 2 * 256 * 768, nullptr, t0, x2b);

    // 3 residual blocks
    for (int i = 0; i < 3; i++) {
        const __nv_bfloat16* wa = wc + (size_t)(3 + 2 * i) * 256 * 768;
        const __nv_bfloat16* wb = wc + (size_t)(4 + 2 * i) * 256 * 768;
        gemm_mma_kernel<<<ggrid, 256, GEMM_SMEM>>>(x2b, wa, nullptr, nullptr, x2a);
        float* dstf = (i == 2) ? out_hu : t0;
        __nv_bfloat16* dst2 = (i == 2) ? nullptr : x2b;
        gemm_mma_kernel<<<ggrid, 256, GEMM_SMEM>>>(x2a, wb, t0, dstf, dst2);
    }
}

// round 5
// speedup vs baseline: 2.4950x; 1.3309x over previous
#include <cuda_runtime.h>
#include <cuda_bf16.h>
#include <math.h>
#include <stdint.h>

// Problem constants (fixed shapes per reference)
#define NN 4096
#define EE 256
#define KK 128
#define BB 64
#define DD 8

// ---------------- scratch (no allocations allowed) ----------------
__device__ float g_t0[NN * EE];
__device__ float g_hres[NN * EE];
__device__ float g_c[NN * KK];
__device__ float g_s[NN * KK];
__device__ float g_sfr[BB * KK * EE];
__device__ float g_sfi[BB * KK * EE];
__device__ float g_kf[KK * EE];
__device__ int   g_off[BB + 1];
// bf16 hi/lo activation buffers: layout (NN, 512) = [hi(256) | lo(256)]
__device__ __nv_bfloat16 g_x2a[NN * 512];
__device__ __nv_bfloat16 g_x2b[NN * 512];
// concatenated weights: 9 matrices, each (256, 768) = [hi | lo | hi] along K
__device__ __nv_bfloat16 g_wc[9 * 256 * 768];

// ---------------- helpers ----------------
__device__ __forceinline__ float silu(float v) {
    return v / (1.0f + __expf(-v));
}

__device__ __forceinline__ uint32_t smem_u32(const void* p) {
    uint32_t a;
    asm("{ .reg .u64 t; cvta.to.shared.u64 t, %1; cvt.u32.u64 %0, t; }" : "=r"(a) : "l"(p));
    return a;
}

#define LDMATRIX_X4(r0, r1, r2, r3, addr) \
    asm volatile("ldmatrix.sync.aligned.m8n8.x4.shared.b16 {%0,%1,%2,%3}, [%4];" \
                 : "=r"(r0), "=r"(r1), "=r"(r2), "=r"(r3) : "r"(addr))

#define MMA_BF16(c, a, b0, b1) \
    asm volatile("mma.sync.aligned.m16n8k16.row.col.f32.bf16.bf16.f32 " \
                 "{%0,%1,%2,%3},{%4,%5,%6,%7},{%8,%9},{%0,%1,%2,%3};" \
                 : "+f"((c)[0]), "+f"((c)[1]), "+f"((c)[2]), "+f"((c)[3]) \
                 : "r"((a)[0]), "r"((a)[1]), "r"((a)[2]), "r"((a)[3]), \
                   "r"(b0), "r"(b1))

#define CP_ASYNC16(dst, src) \
    asm volatile("cp.async.cg.shared.global [%0], [%1], 16;" :: "r"(dst), "l"(src))
#define CP_COMMIT() asm volatile("cp.async.commit_group;" ::: "memory")

// ============================================================================
// HMMA GEMM: out = silu(A @ W^T) [+ skip]
// A2: (NN, 512) bf16 [hi|lo].  Wc: (256, 768) bf16 [hi|lo|hi].
// 3-term split via K=768: Ahi*Whi (k 0-255), Ahi*Wlo (256-511), Alo*Whi (512-767).
// CTA tile 128x64, 512 threads = 16 warps (4m x 4n), warp tile 32x16, BK=64,
// 3-stage cp.async pipeline, smem row stride 144B (ldmatrix conflict-free).
// ============================================================================
#define RSTR  144                 // smem row stride bytes
#define A_BYTES (128 * RSTR)      // 18432
#define B_BYTES (64 * RSTR)       // 9216
#define STG   (A_BYTES + B_BYTES) // 27648
#define GEMM_SMEM (3 * STG)       // 82944

__device__ __forceinline__ void load_chunk(
    uint32_t sb, int stage, int ch,
    const __nv_bfloat16* __restrict__ gA,
    const __nv_bfloat16* __restrict__ gW, int tid)
{
    int k = ch * 64;
    int acol = (k >= 256) ? (k - 256) : k;
    uint32_t base = sb + stage * STG;
#pragma unroll
    for (int l = 0; l < 2; l++) {
        int idx = tid + 512 * l;
        int r = idx >> 3, c = idx & 7;
        CP_ASYNC16(base + r * RSTR + c * 16,
                   gA + (size_t)r * 512 + acol + c * 8);
    }
    if (tid < 512) {
        int r = tid >> 3, c = tid & 7;
        CP_ASYNC16(base + A_BYTES + r * RSTR + c * 16,
                   gW + (size_t)r * 768 + k + c * 8);
    }
    CP_COMMIT();
}

__global__ void __launch_bounds__(512, 1) gemm_mma_kernel(
    const __nv_bfloat16* __restrict__ A2,
    const __nv_bfloat16* __restrict__ Wc,
    const float* __restrict__ skip,
    float* __restrict__ outf,
    __nv_bfloat16* __restrict__ out2)
{
    extern __shared__ char smem[];
    uint32_t sb = smem_u32(smem);

    int tid = threadIdx.x, wid = tid >> 5, lane = tid & 31;
    int m0 = blockIdx.y * 128, n0 = blockIdx.x * 64;
    int warp_m = (wid & 3) * 32, warp_n = (wid >> 2) * 16;

    const __nv_bfloat16* gA = A2 + (size_t)m0 * 512;
    const __nv_bfloat16* gW = Wc + (size_t)n0 * 768;

    float acc[2][2][4];
#pragma unroll
    for (int i = 0; i < 2; i++)
#pragma unroll
        for (int j = 0; j < 2; j++)
#pragma unroll
            for (int q = 0; q < 4; q++) acc[i][j][q] = 0.f;

    // prologue: stages 0,1 in flight
    load_chunk(sb, 0, 0, gA, gW, tid);
    load_chunk(sb, 1, 1, gA, gW, tid);

    int stage = 0;
#pragma unroll 1
    for (int ch = 0; ch < 12; ch++) {
        if (ch < 11) asm volatile("cp.async.wait_group 1;" ::: "memory");
        else         asm volatile("cp.async.wait_group 0;" ::: "memory");
        __syncthreads();  // group ch visible to all; prev stage fully consumed

        if (ch + 2 < 12) {
            int ns = stage + 2; if (ns >= 3) ns -= 3;
            load_chunk(sb, ns, ch + 2, gA, gW, tid);
        }

        uint32_t aB = sb + stage * STG;
        uint32_t bB = aB + A_BYTES;
#pragma unroll
        for (int kh = 0; kh < 4; kh++) {
            uint32_t a[2][4], b[4];
#pragma unroll
            for (int mt = 0; mt < 2; mt++) {
                int row = warp_m + mt * 16 + (lane & 15);
                uint32_t addr = aB + row * RSTR + kh * 32 + (lane >> 4) * 16;
                LDMATRIX_X4(a[mt][0], a[mt][1], a[mt][2], a[mt][3], addr);
            }
            {
                int row = warp_n + (lane & 15);
                uint32_t addr = bB + row * RSTR + kh * 32 + (lane >> 4) * 16;
                LDMATRIX_X4(b[0], b[1], b[2], b[3], addr);
            }
#pragma unroll
            for (int mt = 0; mt < 2; mt++)
#pragma unroll
                for (int j = 0; j < 2; j++) {
                    MMA_BF16(acc[mt][j], a[mt], b[j], b[j + 2]);
                }
        }

        stage++; if (stage >= 3) stage = 0;
    }

    // ---------------- epilogue ----------------
    int r0 = lane >> 2, cp = (lane & 3) * 2;
#pragma unroll
    for (int mt = 0; mt < 2; mt++) {
#pragma unroll
        for (int j = 0; j < 2; j++) {
            int n = n0 + warp_n + j * 8 + cp;
#pragma unroll
            for (int half = 0; half < 2; half++) {
                int m = m0 + warp_m + mt * 16 + r0 + half * 8;
                float v0 = acc[mt][j][half * 2 + 0];
                float v1 = acc[mt][j][half * 2 + 1];
                v0 = silu(v0);
                v1 = silu(v1);
                if (skip) {
                    float2 sk = *reinterpret_cast<const float2*>(skip + (size_t)m * 256 + n);
                    v0 += sk.x; v1 += sk.y;
                }
                if (outf) {
                    float2 o; o.x = v0; o.y = v1;
                    *reinterpret_cast<float2*>(outf + (size_t)m * 256 + n) = o;
                }
                if (out2) {
                    __nv_bfloat16 h0 = __float2bfloat16(v0);
                    __nv_bfloat16 h1 = __float2bfloat16(v1);
                    __nv_bfloat162 hh; hh.x = h0; hh.y = h1;
                    __nv_bfloat162 ll;
                    ll.x = __float2bfloat16(v0 - __bfloat162float(h0));
                    ll.y = __float2bfloat16(v1 - __bfloat162float(h1));
                    *reinterpret_cast<__nv_bfloat162*>(out2 + (size_t)m * 512 + n) = hh;
                    *reinterpret_cast<__nv_bfloat162*>(out2 + (size_t)m * 512 + 256 + n) = ll;
                }
            }
        }
    }
}

// ---------------- hi/lo conversion of h ----------------
__global__ void conv_h_kernel(const float* __restrict__ h) {
    int idx = blockIdx.x * 256 + threadIdx.x;
    int m = idx >> 8, e = idx & 255;
    float v = h[idx];
    __nv_bfloat16 hi = __float2bfloat16(v);
    g_x2a[(size_t)m * 512 + e] = hi;
    g_x2a[(size_t)m * 512 + 256 + e] = __float2bfloat16(v - __bfloat162float(hi));
}

// ---------------- weight concat conversion: 9 x (256, 768) [hi|lo|hi] --------
__global__ void conv_w_kernel(const float* __restrict__ Wpre,
                              const float* __restrict__ W0,
                              const float* __restrict__ Wres) {
    int g = blockIdx.y;
    int i = blockIdx.x * 256 + threadIdx.x;  // 0..65535
    int n = i >> 8, k = i & 255;
    const float* src = (g < 2) ? (Wpre + (size_t)g * 65536)
                     : (g == 2) ? W0
                     : (Wres + (size_t)(g - 3) * 65536);
    float v = src[i];
    __nv_bfloat16 hi = __float2bfloat16(v);
    __nv_bfloat16 lo = __float2bfloat16(v - __bfloat162float(hi));
    __nv_bfloat16* dst = g_wc + (size_t)g * 256 * 768 + (size_t)n * 768;
    dst[k] = hi;
    dst[256 + k] = lo;
    dst[512 + k] = hi;
}

// ---------------- segment offsets from sorted batch_seg ----------------
__global__ void seg_offsets_kernel(const int* __restrict__ seg) {
    int n = blockIdx.x * blockDim.x + threadIdx.x;
    if (n >= NN) return;
    int s = seg[n];
    if (n == 0) {
        for (int b = 0; b <= s; b++) g_off[b] = 0;
    } else {
        int p = seg[n - 1];
        for (int b = p + 1; b <= s; b++) g_off[b] = n;
    }
    if (n == NN - 1) {
        for (int b = s + 1; b <= BB; b++) g_off[b] = NN;
    }
}

// ---------------- dot products + cos/sin ----------------
__global__ void dot_kernel(const float* __restrict__ x,
                           const float* __restrict__ kvec,
                           const int* __restrict__ seg,
                           float* __restrict__ dot_out) {
    int n = blockIdx.x;
    int kk = threadIdx.x;  // 128
    int b = seg[n];
    float x0 = x[n * 3 + 0], x1 = x[n * 3 + 1], x2 = x[n * 3 + 2];
    const float* kr = kvec + ((size_t)b * KK + kk) * 3;
    float d = kr[0] * x0 + kr[1] * x1 + kr[2] * x2;
    dot_out[n * KK + kk] = d;
    float cv, sv;
    sincosf(d, &sv, &cv);
    g_c[n * KK + kk] = cv;
    g_s[n * KK + kk] = sv;
}

// ---------------- low-rank k-filter ----------------
__global__ void kf_kernel(const float* __restrict__ Wup,
                          const float* __restrict__ Wdn) {
    int e = threadIdx.x;
    int k = blockIdx.x;
    float a = 0.f;
#pragma unroll
    for (int d = 0; d < DD; d++) a += Wup[e * DD + d] * Wdn[d * KK + k];
    g_kf[k * EE + e] = a;
}

// ---------------- structure factors (kfilter folded in) ----------------
// block: 256 threads. out tile: k 32 x e 32. thread -> (ky = t>>3, e4 = t&7),
// 4 e-outputs per thread via float4 shared reads.
__global__ void __launch_bounds__(256, 4) sf_kernel() {
    int b  = blockIdx.z;
    int k0 = blockIdx.y * 32;
    int e0 = blockIdx.x * 32;
    int t = threadIdx.x;
    int e4 = t & 7;
    int ky = t >> 3;
    __shared__ float csh[32][32], ssh[32][32], hsh[32][32];
    int st = g_off[b], en = g_off[b + 1];
    float aR[4] = {0.f, 0.f, 0.f, 0.f};
    float aI[4] = {0.f, 0.f, 0.f, 0.f};
    for (int n0 = st; n0 < en; n0 += 32) {
#pragma unroll
        for (int l = 0; l < 4; l++) {
            int idx = t + 256 * l;
            int r = idx >> 5, c = idx & 31;
            int n = n0 + r;
            bool v = (n < en);
            csh[r][c] = v ? g_c[n * KK + k0 + c] : 0.f;
            ssh[r][c] = v ? g_s[n * KK + k0 + c] : 0.f;
            hsh[r][c] = v ? g_hres[(size_t)n * EE + e0 + c] : 0.f;
        }
        __syncthreads();
#pragma unroll
        for (int nn = 0; nn < 32; nn++) {
            float4 hv = *reinterpret_cast<float4*>(&hsh[nn][e4 * 4]);
            float cv = csh[nn][ky];
            float sv = ssh[nn][ky];
            aR[0] += cv * hv.x; aR[1] += cv * hv.y; aR[2] += cv * hv.z; aR[3] += cv * hv.w;
            aI[0] += sv * hv.x; aI[1] += sv * hv.y; aI[2] += sv * hv.z; aI[3] += sv * hv.w;
        }
        __syncthreads();
    }
    float4 f = *reinterpret_cast<float4*>(&g_kf[(k0 + ky) * EE + e0 + e4 * 4]);
    size_t idx = ((size_t)b * KK + k0 + ky) * EE + e0 + e4 * 4;
    float4 oR, oI;
    oR.x = aR[0] * f.x; oR.y = aR[1] * f.y; oR.z = aR[2] * f.z; oR.w = aR[3] * f.w;
    oI.x = aI[0] * f.x; oI.y = aI[1] * f.y; oI.z = aI[2] * f.z; oI.w = aI[3] * f.w;
    *reinterpret_cast<float4*>(&g_sfr[idx]) = oR;
    *reinterpret_cast<float4*>(&g_sfi[idx]) = oI;
}

// ---------------- back-projection; writes hi/lo bf16 of 0.01*acc ------------
// block: 256 threads. out tile: n 32 x e 32. thread -> (ny = t>>3, e4 = t&7),
// 4 e-outputs per thread; sf read as coalesced float4 from L2.
__global__ void __launch_bounds__(256, 4) hupd_kernel(const int* __restrict__ seg) {
    int n0 = blockIdx.y * 32;
    int e0 = blockIdx.x * 32;
    int t = threadIdx.x;
    int e4 = t & 7;
    int ny = t >> 3;
    int n = n0 + ny;
    int b = seg[n];
    __shared__ float csh[32][32], ssh[32][32];
    float acc[4] = {0.f, 0.f, 0.f, 0.f};
    for (int k0c = 0; k0c < KK; k0c += 32) {
#pragma unroll
        for (int l = 0; l < 4; l++) {
            int idx = t + 256 * l;
            int r = idx >> 5, c = idx & 31;
            csh[r][c] = g_c[(n0 + r) * KK + k0c + c];
            ssh[r][c] = g_s[(n0 + r) * KK + k0c + c];
        }
        __syncthreads();
        const float* baseR = g_sfr + ((size_t)b * KK + k0c) * EE + e0 + e4 * 4;
        const float* baseI = g_sfi + ((size_t)b * KK + k0c) * EE + e0 + e4 * 4;
#pragma unroll
        for (int kk = 0; kk < 32; kk++) {
            float cv = csh[ny][kk];
            float sv = ssh[ny][kk];
            float4 pr = *reinterpret_cast<const float4*>(baseR + (size_t)kk * EE);
            float4 pi = *reinterpret_cast<const float4*>(baseI + (size_t)kk * EE);
            acc[0] += cv * pr.x + sv * pi.x;
            acc[1] += cv * pr.y + sv * pi.y;
            acc[2] += cv * pr.z + sv * pi.z;
            acc[3] += cv * pr.w + sv * pi.w;
        }
        __syncthreads();
    }
    __nv_bfloat16 hi[4], lo[4];
#pragma unroll
    for (int q = 0; q < 4; q++) {
        float v = 0.01f * acc[q];
        hi[q] = __float2bfloat16(v);
        lo[q] = __float2bfloat16(v - __bfloat162float(hi[q]));
    }
    *reinterpret_cast<uint2*>(&g_x2a[(size_t)n * 512 + e0 + e4 * 4]) =
        *reinterpret_cast<uint2*>(hi);
    *reinterpret_cast<uint2*>(&g_x2a[(size_t)n * 512 + 256 + e0 + e4 * 4]) =
        *reinterpret_cast<uint2*>(lo);
}

// ---------------- launch ----------------
extern "C" void kernel_launch(void* const* d_in, const int* in_sizes, int n_in,
                              void* d_out, int out_size) {
    const float *h = nullptr, *x = nullptr, *kv = nullptr;
    const float *Wpre = nullptr, *Wdn = nullptr, *Wup = nullptr;
    const float *W0 = nullptr, *Wres = nullptr;
    const int* seg = nullptr;

    for (int i = 0; i < n_in; i++) {
        switch (in_sizes[i]) {
            case NN * EE:           h    = (const float*)d_in[i]; break;
            case NN * 3:            x    = (const float*)d_in[i]; break;
            case BB * KK * 3:       kv   = (const float*)d_in[i]; break;
            case NN:                seg  = (const int*)d_in[i];   break;
            case 2 * EE * EE:       Wpre = (const float*)d_in[i]; break;
            case DD * KK:           Wdn  = (const float*)d_in[i]; break;
            case EE * DD:           Wup  = (const float*)d_in[i]; break;
            case EE * EE:           W0   = (const float*)d_in[i]; break;
            case 3 * 2 * EE * EE:   Wres = (const float*)d_in[i]; break;
            default: break;
        }
    }

    float* out = (float*)d_out;
    float* out_hu  = out;            // (NN, EE)
    float* out_dot = out + NN * EE;  // (NN, KK)

    float *t0, *hres;
    __nv_bfloat16 *x2a, *x2b, *wc;
    cudaGetSymbolAddress((void**)&t0,   g_t0);
    cudaGetSymbolAddress((void**)&hres, g_hres);
    cudaGetSymbolAddress((void**)&x2a,  g_x2a);
    cudaGetSymbolAddress((void**)&x2b,  g_x2b);
    cudaGetSymbolAddress((void**)&wc,   g_wc);

    cudaFuncSetAttribute(gemm_mma_kernel,
                         cudaFuncAttributeMaxDynamicSharedMemorySize, GEMM_SMEM);
    dim3 ggrid(EE / 64, NN / 128);  // (4, 32) = 128 CTAs

    // conversions
    conv_w_kernel<<<dim3(256, 9), 256>>>(Wpre, W0, Wres);
    conv_h_kernel<<<NN * EE / 256, 256>>>(h);

    // pre-residual: x2b = silu(h@W0'), hres = h + silu(x2b@W1')
    gemm_mma_kernel<<<ggrid, 512, GEMM_SMEM>>>(x2a, wc + 0 * 256 * 768, nullptr, nullptr, x2b);
    gemm_mma_kernel<<<ggrid, 512, GEMM_SMEM>>>(x2b, wc + 1 * 256 * 768, h, hres, nullptr);

    // Ewald geometry path
    seg_offsets_kernel<<<(NN + 255) / 256, 256>>>(seg);
    dot_kernel<<<NN, KK>>>(x, kv, seg, out_dot);
    kf_kernel<<<KK, EE>>>(Wup, Wdn);
    sf_kernel<<<dim3(EE / 32, KK / 32, BB), 256>>>();
    hupd_kernel<<<dim3(EE / 32, NN / 32), 256>>>(seg);  // -> g_x2a (hi/lo)

    // update MLP: t0 = silu(hu @ W0^T) (fp32 copy needed as residual skip)
    gemm_mma_kernel<<<ggrid, 512, GEMM_SMEM>>>(x2a, wc + 2 * 256 * 768, nullptr, t0, x2b);

    // 3 residual blocks
    for (int i = 0; i < 3; i++) {
        const __nv_bfloat16* wa = wc + (size_t)(3 + 2 * i) * 256 * 768;
        const __nv_bfloat16* wb = wc + (size_t)(4 + 2 * i) * 256 * 768;
        gemm_mma_kernel<<<ggrid, 512, GEMM_SMEM>>>(x2b, wa, nullptr, nullptr, x2a);
        float* dstf = (i == 2) ? out_hu : t0;
        __nv_bfloat16* dst2 = (i == 2) ? nullptr : x2b;
        gemm_mma_kernel<<<ggrid, 512, GEMM_SMEM>>>(x2a, wb, t0, dstf, dst2);
    }
}

// round 6
// speedup vs baseline: 2.5757x; 1.0323x over previous
#include <cuda_runtime.h>
#include <cuda_bf16.h>
#include <math.h>
#include <stdint.h>

// Problem constants (fixed shapes per reference)
#define NN 4096
#define EE 256
#define KK 128
#define BB 64
#define DD 8

// ---------------- scratch (no allocations allowed) ----------------
__device__ float g_t0[NN * EE];
__device__ float g_hres[NN * EE];
__device__ float g_c[NN * KK];
__device__ float g_s[NN * KK];
__device__ float g_sfr[BB * KK * EE];
__device__ float g_sfi[BB * KK * EE];
__device__ float g_kf[KK * EE];
__device__ int   g_off[BB + 1];
// bf16 hi/lo activation buffers: layout (NN, 512) = [hi(256) | lo(256)]
__device__ __nv_bfloat16 g_x2a[NN * 512];
__device__ __nv_bfloat16 g_x2b[NN * 512];
// concatenated weights: 9 matrices, each (256, 512) = [hi | lo] along K (unique)
__device__ __nv_bfloat16 g_wc[9 * 256 * 512];

// ---------------- helpers ----------------
__device__ __forceinline__ float silu(float v) {
    return v / (1.0f + __expf(-v));
}

__device__ __forceinline__ uint32_t smem_u32(const void* p) {
    uint32_t a;
    asm("{ .reg .u64 t; cvta.to.shared.u64 t, %1; cvt.u32.u64 %0, t; }" : "=r"(a) : "l"(p));
    return a;
}

#define LDMATRIX_X4(r0, r1, r2, r3, addr) \
    asm volatile("ldmatrix.sync.aligned.m8n8.x4.shared.b16 {%0,%1,%2,%3}, [%4];" \
                 : "=r"(r0), "=r"(r1), "=r"(r2), "=r"(r3) : "r"(addr))

#define MMA_BF16(c, a, b0, b1) \
    asm volatile("mma.sync.aligned.m16n8k16.row.col.f32.bf16.bf16.f32 " \
                 "{%0,%1,%2,%3},{%4,%5,%6,%7},{%8,%9},{%0,%1,%2,%3};" \
                 : "+f"((c)[0]), "+f"((c)[1]), "+f"((c)[2]), "+f"((c)[3]) \
                 : "r"((a)[0]), "r"((a)[1]), "r"((a)[2]), "r"((a)[3]), \
                   "r"(b0), "r"(b1))

#define CP_ASYNC16(dst, src) \
    asm volatile("cp.async.cg.shared.global [%0], [%1], 16;" :: "r"(dst), "l"(src))
#define CP_COMMIT() asm volatile("cp.async.commit_group;" ::: "memory")

// ============================================================================
// HMMA GEMM, W-persistent: out = silu(A @ W^T) [+ skip]
// A2: (NN, 512) bf16 [hi|lo].  Wc: (256, 512) bf16 [hi|lo] (unique).
// 3-term split: Ahi*Whi + Ahi*Wlo + Alo*Whi.
// CTA tile 128x64, 512 threads = 16 warps (4m x 4n), warp tile 32x16.
// W slice (64x512) persistent in smem (stride 1040B, ldmatrix conflict-free);
// A streamed as 8 unique 16KB chunks through a 3-stage cp.async ring.
// Each Ahi chunk feeds 2 MMA sets (Whi + Wlo); Alo chunks feed 1 (Whi).
// ============================================================================
#define WSTR   1040                 // W persist row stride bytes (520 bf16)
#define W_PBYTES (64 * WSTR)        // 66560
#define RSTR   144                  // A stage row stride bytes
#define A_ST   (128 * RSTR)         // 18432
#define GEMM_SMEM (W_PBYTES + 3 * A_ST)  // 121856

__device__ __forceinline__ void load_a_chunk(
    uint32_t sb, int stage, int ch,
    const __nv_bfloat16* __restrict__ gA, int tid)
{
    int a_off = (ch < 4) ? ch * 64 : 256 + (ch - 4) * 64;
    uint32_t base = sb + W_PBYTES + stage * A_ST;
#pragma unroll
    for (int l = 0; l < 2; l++) {
        int idx = tid + 512 * l;
        int r = idx >> 3, c = idx & 7;
        CP_ASYNC16(base + r * RSTR + c * 16,
                   gA + (size_t)r * 512 + a_off + c * 8);
    }
    CP_COMMIT();
}

__global__ void __launch_bounds__(512, 1) gemm_mma_kernel(
    const __nv_bfloat16* __restrict__ A2,
    const __nv_bfloat16* __restrict__ Wc,
    const float* __restrict__ skip,
    float* __restrict__ outf,
    __nv_bfloat16* __restrict__ out2)
{
    extern __shared__ char smem[];
    uint32_t sb = smem_u32(smem);

    int tid = threadIdx.x, wid = tid >> 5, lane = tid & 31;
    int m0 = blockIdx.y * 128, n0 = blockIdx.x * 64;
    int warp_m = (wid & 3) * 32, warp_n = (wid >> 2) * 16;

    const __nv_bfloat16* gA = A2 + (size_t)m0 * 512;
    const __nv_bfloat16* gW = Wc + (size_t)n0 * 512;

    float acc[2][2][4];
#pragma unroll
    for (int i = 0; i < 2; i++)
#pragma unroll
        for (int j = 0; j < 2; j++)
#pragma unroll
            for (int q = 0; q < 4; q++) acc[i][j][q] = 0.f;

    // prologue: W persistent load (group 0), A chunks 0,1 (groups 1,2)
#pragma unroll
    for (int l = 0; l < 8; l++) {
        int idx = tid + 512 * l;          // 0..4095
        int r = idx >> 6, c = idx & 63;   // 64 rows x 64 x 16B
        CP_ASYNC16(sb + r * WSTR + c * 16,
                   gW + (size_t)r * 512 + c * 8);
    }
    CP_COMMIT();
    load_a_chunk(sb, 0, 0, gA, tid);
    load_a_chunk(sb, 1, 1, gA, tid);

#pragma unroll 1
    for (int ch = 0; ch < 8; ch++) {
        if (ch < 7) asm volatile("cp.async.wait_group 1;" ::: "memory");
        else        asm volatile("cp.async.wait_group 0;" ::: "memory");
        __syncthreads();

        if (ch + 2 < 8) load_a_chunk(sb, (ch + 2) % 3, ch + 2, gA, tid);

        uint32_t aB = sb + W_PBYTES + (ch % 3) * A_ST;
        bool isHi = (ch < 4);
        int whi = (isHi ? ch : (ch - 4)) * 128;   // byte col of Whi block
        int wlo = 512 + ch * 128;                  // byte col of Wlo block (ch<4)

#pragma unroll
        for (int kh = 0; kh < 4; kh++) {
            uint32_t a[2][4], bh[4];
#pragma unroll
            for (int mt = 0; mt < 2; mt++) {
                int row = warp_m + mt * 16 + (lane & 15);
                uint32_t addr = aB + row * RSTR + kh * 32 + (lane >> 4) * 16;
                LDMATRIX_X4(a[mt][0], a[mt][1], a[mt][2], a[mt][3], addr);
            }
            int brow = warp_n + (lane & 15);
            {
                uint32_t addr = sb + brow * WSTR + whi + kh * 32 + (lane >> 4) * 16;
                LDMATRIX_X4(bh[0], bh[1], bh[2], bh[3], addr);
            }
#pragma unroll
            for (int mt = 0; mt < 2; mt++)
#pragma unroll
                for (int j = 0; j < 2; j++)
                    MMA_BF16(acc[mt][j], a[mt], bh[j], bh[j + 2]);

            if (isHi) {
                uint32_t bl[4];
                uint32_t addr = sb + brow * WSTR + wlo + kh * 32 + (lane >> 4) * 16;
                LDMATRIX_X4(bl[0], bl[1], bl[2], bl[3], addr);
#pragma unroll
                for (int mt = 0; mt < 2; mt++)
#pragma unroll
                    for (int j = 0; j < 2; j++)
                        MMA_BF16(acc[mt][j], a[mt], bl[j], bl[j + 2]);
            }
        }
    }

    // ---------------- epilogue ----------------
    int r0 = lane >> 2, cp = (lane & 3) * 2;
#pragma unroll
    for (int mt = 0; mt < 2; mt++) {
#pragma unroll
        for (int j = 0; j < 2; j++) {
            int n = n0 + warp_n + j * 8 + cp;
#pragma unroll
            for (int half = 0; half < 2; half++) {
                int m = m0 + warp_m + mt * 16 + r0 + half * 8;
                float v0 = acc[mt][j][half * 2 + 0];
                float v1 = acc[mt][j][half * 2 + 1];
                v0 = silu(v0);
                v1 = silu(v1);
                if (skip) {
                    float2 sk = *reinterpret_cast<const float2*>(skip + (size_t)m * 256 + n);
                    v0 += sk.x; v1 += sk.y;
                }
                if (outf) {
                    float2 o; o.x = v0; o.y = v1;
                    *reinterpret_cast<float2*>(outf + (size_t)m * 256 + n) = o;
                }
                if (out2) {
                    __nv_bfloat16 h0 = __float2bfloat16(v0);
                    __nv_bfloat16 h1 = __float2bfloat16(v1);
                    __nv_bfloat162 hh; hh.x = h0; hh.y = h1;
                    __nv_bfloat162 ll;
                    ll.x = __float2bfloat16(v0 - __bfloat162float(h0));
                    ll.y = __float2bfloat16(v1 - __bfloat162float(h1));
                    *reinterpret_cast<__nv_bfloat162*>(out2 + (size_t)m * 512 + n) = hh;
                    *reinterpret_cast<__nv_bfloat162*>(out2 + (size_t)m * 512 + 256 + n) = ll;
                }
            }
        }
    }
}

// ---------------- hi/lo conversion of h ----------------
__global__ void conv_h_kernel(const float* __restrict__ h) {
    int idx = blockIdx.x * 256 + threadIdx.x;
    int m = idx >> 8, e = idx & 255;
    float v = h[idx];
    __nv_bfloat16 hi = __float2bfloat16(v);
    g_x2a[(size_t)m * 512 + e] = hi;
    g_x2a[(size_t)m * 512 + 256 + e] = __float2bfloat16(v - __bfloat162float(hi));
}

// ---------------- weight conversion: 9 x (256, 512) [hi|lo] ----------------
__global__ void conv_w_kernel(const float* __restrict__ Wpre,
                              const float* __restrict__ W0,
                              const float* __restrict__ Wres) {
    int g = blockIdx.y;
    int i = blockIdx.x * 256 + threadIdx.x;  // 0..65535
    int n = i >> 8, k = i & 255;
    const float* src = (g < 2) ? (Wpre + (size_t)g * 65536)
                     : (g == 2) ? W0
                     : (Wres + (size_t)(g - 3) * 65536);
    float v = src[i];
    __nv_bfloat16 hi = __float2bfloat16(v);
    __nv_bfloat16 lo = __float2bfloat16(v - __bfloat162float(hi));
    __nv_bfloat16* dst = g_wc + (size_t)g * 256 * 512 + (size_t)n * 512;
    dst[k] = hi;
    dst[256 + k] = lo;
}

// ---------------- segment offsets from sorted batch_seg ----------------
__global__ void seg_offsets_kernel(const int* __restrict__ seg) {
    int n = blockIdx.x * blockDim.x + threadIdx.x;
    if (n >= NN) return;
    int s = seg[n];
    if (n == 0) {
        for (int b = 0; b <= s; b++) g_off[b] = 0;
    } else {
        int p = seg[n - 1];
        for (int b = p + 1; b <= s; b++) g_off[b] = n;
    }
    if (n == NN - 1) {
        for (int b = s + 1; b <= BB; b++) g_off[b] = NN;
    }
}

// ---------------- dot products + cos/sin ----------------
__global__ void dot_kernel(const float* __restrict__ x,
                           const float* __restrict__ kvec,
                           const int* __restrict__ seg,
                           float* __restrict__ dot_out) {
    int n = blockIdx.x;
    int kk = threadIdx.x;  // 128
    int b = seg[n];
    float x0 = x[n * 3 + 0], x1 = x[n * 3 + 1], x2 = x[n * 3 + 2];
    const float* kr = kvec + ((size_t)b * KK + kk) * 3;
    float d = kr[0] * x0 + kr[1] * x1 + kr[2] * x2;
    dot_out[n * KK + kk] = d;
    float cv, sv;
    sincosf(d, &sv, &cv);
    g_c[n * KK + kk] = cv;
    g_s[n * KK + kk] = sv;
}

// ---------------- low-rank k-filter ----------------
__global__ void kf_kernel(const float* __restrict__ Wup,
                          const float* __restrict__ Wdn) {
    int e = threadIdx.x;
    int k = blockIdx.x;
    float a = 0.f;
#pragma unroll
    for (int d = 0; d < DD; d++) a += Wup[e * DD + d] * Wdn[d * KK + k];
    g_kf[k * EE + e] = a;
}

// ---------------- structure factors (kfilter folded in) ----------------
__global__ void __launch_bounds__(256, 4) sf_kernel() {
    int b  = blockIdx.z;
    int k0 = blockIdx.y * 32;
    int e0 = blockIdx.x * 32;
    int t = threadIdx.x;
    int e4 = t & 7;
    int ky = t >> 3;
    __shared__ float csh[32][32], ssh[32][32], hsh[32][32];
    int st = g_off[b], en = g_off[b + 1];
    float aR[4] = {0.f, 0.f, 0.f, 0.f};
    float aI[4] = {0.f, 0.f, 0.f, 0.f};
    for (int n0 = st; n0 < en; n0 += 32) {
#pragma unroll
        for (int l = 0; l < 4; l++) {
            int idx = t + 256 * l;
            int r = idx >> 5, c = idx & 31;
            int n = n0 + r;
            bool v = (n < en);
            csh[r][c] = v ? g_c[n * KK + k0 + c] : 0.f;
            ssh[r][c] = v ? g_s[n * KK + k0 + c] : 0.f;
            hsh[r][c] = v ? g_hres[(size_t)n * EE + e0 + c] : 0.f;
        }
        __syncthreads();
#pragma unroll
        for (int nn = 0; nn < 32; nn++) {
            float4 hv = *reinterpret_cast<float4*>(&hsh[nn][e4 * 4]);
            float cv = csh[nn][ky];
            float sv = ssh[nn][ky];
            aR[0] += cv * hv.x; aR[1] += cv * hv.y; aR[2] += cv * hv.z; aR[3] += cv * hv.w;
            aI[0] += sv * hv.x; aI[1] += sv * hv.y; aI[2] += sv * hv.z; aI[3] += sv * hv.w;
        }
        __syncthreads();
    }
    float4 f = *reinterpret_cast<float4*>(&g_kf[(k0 + ky) * EE + e0 + e4 * 4]);
    size_t idx = ((size_t)b * KK + k0 + ky) * EE + e0 + e4 * 4;
    float4 oR, oI;
    oR.x = aR[0] * f.x; oR.y = aR[1] * f.y; oR.z = aR[2] * f.z; oR.w = aR[3] * f.w;
    oI.x = aI[0] * f.x; oI.y = aI[1] * f.y; oI.z = aI[2] * f.z; oI.w = aI[3] * f.w;
    *reinterpret_cast<float4*>(&g_sfr[idx]) = oR;
    *reinterpret_cast<float4*>(&g_sfi[idx]) = oI;
}

// ---------------- back-projection; writes hi/lo bf16 of 0.01*acc ------------
__global__ void __launch_bounds__(256, 4) hupd_kernel(const int* __restrict__ seg) {
    int n0 = blockIdx.y * 32;
    int e0 = blockIdx.x * 32;
    int t = threadIdx.x;
    int e4 = t & 7;
    int ny = t >> 3;
    int n = n0 + ny;
    int b = seg[n];
    __shared__ float csh[32][32], ssh[32][32];
    float acc[4] = {0.f, 0.f, 0.f, 0.f};
    for (int k0c = 0; k0c < KK; k0c += 32) {
#pragma unroll
        for (int l = 0; l < 4; l++) {
            int idx = t + 256 * l;
            int r = idx >> 5, c = idx & 31;
            csh[r][c] = g_c[(n0 + r) * KK + k0c + c];
            ssh[r][c] = g_s[(n0 + r) * KK + k0c + c];
        }
        __syncthreads();
        const float* baseR = g_sfr + ((size_t)b * KK + k0c) * EE + e0 + e4 * 4;
        const float* baseI = g_sfi + ((size_t)b * KK + k0c) * EE + e0 + e4 * 4;
#pragma unroll
        for (int kk = 0; kk < 32; kk++) {
            float cv = csh[ny][kk];
            float sv = ssh[ny][kk];
            float4 pr = *reinterpret_cast<const float4*>(baseR + (size_t)kk * EE);
            float4 pi = *reinterpret_cast<const float4*>(baseI + (size_t)kk * EE);
            acc[0] += cv * pr.x + sv * pi.x;
            acc[1] += cv * pr.y + sv * pi.y;
            acc[2] += cv * pr.z + sv * pi.z;
            acc[3] += cv * pr.w + sv * pi.w;
        }
        __syncthreads();
    }
    __nv_bfloat16 hi[4], lo[4];
#pragma unroll
    for (int q = 0; q < 4; q++) {
        float v = 0.01f * acc[q];
        hi[q] = __float2bfloat16(v);
        lo[q] = __float2bfloat16(v - __bfloat162float(hi[q]));
    }
    *reinterpret_cast<uint2*>(&g_x2a[(size_t)n * 512 + e0 + e4 * 4]) =
        *reinterpret_cast<uint2*>(hi);
    *reinterpret_cast<uint2*>(&g_x2a[(size_t)n * 512 + 256 + e0 + e4 * 4]) =
        *reinterpret_cast<uint2*>(lo);
}

// ---------------- launch ----------------
extern "C" void kernel_launch(void* const* d_in, const int* in_sizes, int n_in,
                              void* d_out, int out_size) {
    const float *h = nullptr, *x = nullptr, *kv = nullptr;
    const float *Wpre = nullptr, *Wdn = nullptr, *Wup = nullptr;
    const float *W0 = nullptr, *Wres = nullptr;
    const int* seg = nullptr;

    for (int i = 0; i < n_in; i++) {
        switch (in_sizes[i]) {
            case NN * EE:           h    = (const float*)d_in[i]; break;
            case NN * 3:            x    = (const float*)d_in[i]; break;
            case BB * KK * 3:       kv   = (const float*)d_in[i]; break;
            case NN:                seg  = (const int*)d_in[i];   break;
            case 2 * EE * EE:       Wpre = (const float*)d_in[i]; break;
            case DD * KK:           Wdn  = (const float*)d_in[i]; break;
            case EE * DD:           Wup  = (const float*)d_in[i]; break;
            case EE * EE:           W0   = (const float*)d_in[i]; break;
            case 3 * 2 * EE * EE:   Wres = (const float*)d_in[i]; break;
            default: break;
        }
    }

    float* out = (float*)d_out;
    float* out_hu  = out;            // (NN, EE)
    float* out_dot = out + NN * EE;  // (NN, KK)

    float *t0, *hres;
    __nv_bfloat16 *x2a, *x2b, *wc;
    cudaGetSymbolAddress((void**)&t0,   g_t0);
    cudaGetSymbolAddress((void**)&hres, g_hres);
    cudaGetSymbolAddress((void**)&x2a,  g_x2a);
    cudaGetSymbolAddress((void**)&x2b,  g_x2b);
    cudaGetSymbolAddress((void**)&wc,   g_wc);

    cudaFuncSetAttribute(gemm_mma_kernel,
                         cudaFuncAttributeMaxDynamicSharedMemorySize, GEMM_SMEM);
    dim3 ggrid(EE / 64, NN / 128);  // (4, 32) = 128 CTAs

    // conversions
    conv_w_kernel<<<dim3(256, 9), 256>>>(Wpre, W0, Wres);
    conv_h_kernel<<<NN * EE / 256, 256>>>(h);

    // pre-residual: x2b = silu(h@W0'), hres = h + silu(x2b@W1')
    gemm_mma_kernel<<<ggrid, 512, GEMM_SMEM>>>(x2a, wc + 0 * 256 * 512, nullptr, nullptr, x2b);
    gemm_mma_kernel<<<ggrid, 512, GEMM_SMEM>>>(x2b, wc + 1 * 256 * 512, h, hres, nullptr);

    // Ewald geometry path
    seg_offsets_kernel<<<(NN + 255) / 256, 256>>>(seg);
    dot_kernel<<<NN, KK>>>(x, kv, seg, out_dot);
    kf_kernel<<<KK, EE>>>(Wup, Wdn);
    sf_kernel<<<dim3(EE / 32, KK / 32, BB), 256>>>();
    hupd_kernel<<<dim3(EE / 32, NN / 32), 256>>>(seg);  // -> g_x2a (hi/lo)

    // update MLP: t0 = silu(hu @ W0^T)
    gemm_mma_kernel<<<ggrid, 512, GEMM_SMEM>>>(x2a, wc + 2 * 256 * 512, nullptr, t0, x2b);

    // 3 residual blocks
    for (int i = 0; i < 3; i++) {
        const __nv_bfloat16* wa = wc + (size_t)(3 + 2 * i) * 256 * 512;
        const __nv_bfloat16* wb = wc + (size_t)(4 + 2 * i) * 256 * 512;
        gemm_mma_kernel<<<ggrid, 512, GEMM_SMEM>>>(x2b, wa, nullptr, nullptr, x2a);
        float* dstf = (i == 2) ? out_hu : t0;
        __nv_bfloat16* dst2 = (i == 2) ? nullptr : x2b;
        gemm_mma_kernel<<<ggrid, 512, GEMM_SMEM>>>(x2a, wb, t0, dstf, dst2);
    }
}

// round 7
// speedup vs baseline: 2.8021x; 1.0879x over previous
#include <cuda_runtime.h>
#include <cuda_bf16.h>
#include <math.h>
#include <stdint.h>

// Problem constants (fixed shapes per reference)
#define NN 4096
#define EE 256
#define KK 128
#define BB 64
#define DD 8

// ---------------- scratch (no allocations allowed) ----------------
__device__ float g_t0[NN * EE];
__device__ float g_hres[NN * EE];
__device__ float g_c[NN * KK];
__device__ float g_s[NN * KK];
__device__ float g_sfr[BB * KK * EE];
__device__ float g_sfi[BB * KK * EE];
__device__ float g_kf[KK * EE];
__device__ int   g_off[BB + 1];
// Activations, SLAB layout: 8 slabs [c][4096 rows][64 bf16 = 128B], SW128-swizzled.
// slabs 0-3 = hi cols 0..255, slabs 4-7 = lo cols 0..255.
__device__ __align__(128) __nv_bfloat16 g_x2a[NN * 512];
__device__ __align__(128) __nv_bfloat16 g_x2b[NN * 512];
// Weights, SLAB layout: 9 gemms x [nblk 4][c 8][64 rows][64 bf16], swizzled.
// c 0-3 = Whi, c 4-7 = Wlo.
__device__ __align__(128) __nv_bfloat16 g_wc[9 * 256 * 512];

// ---------------- helpers ----------------
__device__ __forceinline__ float silu(float v) {
    return v / (1.0f + __expf(-v));
}

__device__ __forceinline__ uint32_t smem_u32(const void* p) {
    uint32_t a;
    asm("{ .reg .u64 t; cvta.to.shared.u64 t, %1; cvt.u32.u64 %0, t; }" : "=r"(a) : "l"(p));
    return a;
}

#define SWZ(o) ((o) ^ (((o) >> 3) & 0x70))

#define LDMATRIX_X4(r0, r1, r2, r3, addr) \
    asm volatile("ldmatrix.sync.aligned.m8n8.x4.shared.b16 {%0,%1,%2,%3}, [%4];" \
                 : "=r"(r0), "=r"(r1), "=r"(r2), "=r"(r3) : "r"(addr))

#define MMA_BF16(c, a, b0, b1) \
    asm volatile("mma.sync.aligned.m16n8k16.row.col.f32.bf16.bf16.f32 " \
                 "{%0,%1,%2,%3},{%4,%5,%6,%7},{%8,%9},{%0,%1,%2,%3};" \
                 : "+f"((c)[0]), "+f"((c)[1]), "+f"((c)[2]), "+f"((c)[3]) \
                 : "r"((a)[0]), "r"((a)[1]), "r"((a)[2]), "r"((a)[3]), \
                   "r"(b0), "r"(b1))

#define MBAR_INIT(a, c) \
    asm volatile("mbarrier.init.shared.b64 [%0], %1;" :: "r"(a), "r"((uint32_t)(c)) : "memory")

#define MBAR_EXPECT_TX(a, n) \
    asm volatile("mbarrier.arrive.expect_tx.shared.b64 _, [%0], %1;" \
                 :: "r"(a), "r"((uint32_t)(n)) : "memory")

#define MBAR_WAIT(addr, ph) do { \
    uint32_t _m = (addr), _p = (uint32_t)(ph), _d; \
    asm volatile("{\n\t.reg .pred p;\n\tmbarrier.try_wait.parity.acquire.cta.shared::cta.b64 p, [%1], %2;\n\tselp.b32 %0, 1, 0, p;\n\t}" \
        : "=r"(_d) : "r"(_m), "r"(_p) : "memory"); \
    if (!_d) { \
        asm volatile("{\n\t.reg .pred P1;\n\tWL_%=:\n\tmbarrier.try_wait.parity.acquire.cta.shared::cta.b64 P1, [%0], %1, 0x989680;\n\t@P1 bra.uni WD_%=;\n\tbra.uni WL_%=;\n\tWD_%=:\n\t}" \
            :: "r"(_m), "r"(_p) : "memory"); \
    } \
} while (0)

#define CP_BULK(dst, src, bytes, mbar) \
    asm volatile("cp.async.bulk.shared::cta.global.mbarrier::complete_tx::bytes " \
                 "[%0], [%1], %2, [%3];" \
                 :: "r"(dst), "l"(src), "r"((uint32_t)(bytes)), "r"(mbar) : "memory")

// ============================================================================
// HMMA GEMM, W-persistent, bulk-copy loads: out = silu(A @ W^T) [+ skip]
// A2: slabbed (8 x [4096][128B], swizzled).  Wc: slabbed per-nblk 64KB.
// 3-term split: Ahi*Whi + Ahi*Wlo + Alo*Whi.
// CTA tile 128x64, 512 threads = 16 warps (4m x 4n), warp tile 32x16.
// W slice: ONE 64KB cp.async.bulk. A: 8 x 16KB bulk through 3-stage ring.
// ============================================================================
#define ASLAB (4096 * 128)          // bytes per activation slab (512KB)
#define A_ST  16384                  // A stage bytes (128 rows x 128B)
#define W_PB  65536                  // W persistent bytes (8 slabs x 8KB)
#define GEMM_SMEM (W_PB + 3 * A_ST)  // 114688

__global__ void __launch_bounds__(512, 1) gemm_mma_kernel(
    const __nv_bfloat16* __restrict__ A2,
    const __nv_bfloat16* __restrict__ Wc,   // already offset to this gemm
    const float* __restrict__ skip,
    float* __restrict__ outf,
    __nv_bfloat16* __restrict__ out2)
{
    extern __shared__ char smem[];
    uint32_t sb = smem_u32(smem);            // [0,65536): W; then 3 A stages
    __shared__ __align__(8) uint64_t mbars[4];  // 0-2: A stages, 3: W

    int tid = threadIdx.x, wid = tid >> 5, lane = tid & 31;
    int m0 = blockIdx.y * 128, n0 = blockIdx.x * 64;
    int nb = blockIdx.x;
    int warp_m = (wid & 3) * 32, warp_n = (wid >> 2) * 16;

    uint32_t mb[3] = { smem_u32(&mbars[0]), smem_u32(&mbars[1]), smem_u32(&mbars[2]) };
    uint32_t wbar  = smem_u32(&mbars[3]);

    if (tid == 0) {
        MBAR_INIT(mb[0], 1);
        MBAR_INIT(mb[1], 1);
        MBAR_INIT(mb[2], 1);
        MBAR_INIT(wbar, 1);
    }
    __syncthreads();

    const char* gA = (const char*)A2 + (size_t)m0 * 128;   // + c*ASLAB per chunk
    const char* gW = (const char*)Wc + (size_t)nb * W_PB;

    if (tid == 0) {
        MBAR_EXPECT_TX(wbar, W_PB);
        CP_BULK(sb, gW, W_PB, wbar);
        MBAR_EXPECT_TX(mb[0], A_ST);
        CP_BULK(sb + W_PB, gA + 0 * (size_t)ASLAB, A_ST, mb[0]);
        MBAR_EXPECT_TX(mb[1], A_ST);
        CP_BULK(sb + W_PB + A_ST, gA + 1 * (size_t)ASLAB, A_ST, mb[1]);
    }

    float acc[2][2][4];
#pragma unroll
    for (int i = 0; i < 2; i++)
#pragma unroll
        for (int j = 0; j < 2; j++)
#pragma unroll
            for (int q = 0; q < 4; q++) acc[i][j][q] = 0.f;

    MBAR_WAIT(wbar, 0);

#pragma unroll
    for (int ch = 0; ch < 8; ch++) {
        const int s = ch % 3;
        MBAR_WAIT(mb[s], (ch / 3) & 1);

        uint32_t aB = sb + W_PB + s * A_ST;
        const bool isHi = (ch < 4);
        const int whiSlab = (isHi ? ch : (ch - 4)) * 8192;
        const int wloSlab = (4 + ch) * 8192;

#pragma unroll
        for (int kh = 0; kh < 4; kh++) {
            uint32_t a[2][4], bh[4];
#pragma unroll
            for (int mt = 0; mt < 2; mt++) {
                int row = warp_m + mt * 16 + (lane & 15);
                uint32_t o = row * 128 + kh * 32 + (lane >> 4) * 16;
                LDMATRIX_X4(a[mt][0], a[mt][1], a[mt][2], a[mt][3], aB + SWZ(o));
            }
            int brow = warp_n + (lane & 15);
            uint32_t bo = brow * 128 + kh * 32 + (lane >> 4) * 16;
            LDMATRIX_X4(bh[0], bh[1], bh[2], bh[3], sb + whiSlab + SWZ(bo));
#pragma unroll
            for (int mt = 0; mt < 2; mt++)
#pragma unroll
                for (int j = 0; j < 2; j++)
                    MMA_BF16(acc[mt][j], a[mt], bh[j], bh[j + 2]);

            if (isHi) {
                uint32_t bl[4];
                LDMATRIX_X4(bl[0], bl[1], bl[2], bl[3], sb + wloSlab + SWZ(bo));
#pragma unroll
                for (int mt = 0; mt < 2; mt++)
#pragma unroll
                    for (int j = 0; j < 2; j++)
                        MMA_BF16(acc[mt][j], a[mt], bl[j], bl[j + 2]);
            }
        }

        __syncthreads();
        if (ch + 2 < 8 && tid == 0) {
            int ns = (ch + 2) % 3;
            MBAR_EXPECT_TX(mb[ns], A_ST);
            CP_BULK(sb + W_PB + ns * A_ST, gA + (size_t)(ch + 2) * ASLAB, A_ST, mb[ns]);
        }
    }

    // ---------------- epilogue ----------------
    char* o2 = (char*)out2;
    int r0 = lane >> 2, cp = (lane & 3) * 2;
#pragma unroll
    for (int mt = 0; mt < 2; mt++) {
#pragma unroll
        for (int j = 0; j < 2; j++) {
            int n = n0 + warp_n + j * 8 + cp;
#pragma unroll
            for (int half = 0; half < 2; half++) {
                int m = m0 + warp_m + mt * 16 + r0 + half * 8;
                float v0 = acc[mt][j][half * 2 + 0];
                float v1 = acc[mt][j][half * 2 + 1];
                v0 = silu(v0);
                v1 = silu(v1);
                if (skip) {
                    float2 sk = *reinterpret_cast<const float2*>(skip + (size_t)m * 256 + n);
                    v0 += sk.x; v1 += sk.y;
                }
                if (outf) {
                    float2 o; o.x = v0; o.y = v1;
                    *reinterpret_cast<float2*>(outf + (size_t)m * 256 + n) = o;
                }
                if (out2) {
                    __nv_bfloat16 h0 = __float2bfloat16(v0);
                    __nv_bfloat16 h1 = __float2bfloat16(v1);
                    __nv_bfloat162 hh; hh.x = h0; hh.y = h1;
                    __nv_bfloat162 ll;
                    ll.x = __float2bfloat16(v0 - __bfloat162float(h0));
                    ll.y = __float2bfloat16(v1 - __bfloat162float(h1));
                    uint32_t loc = SWZ((uint32_t)(m * 128 + (n & 63) * 2));
                    *reinterpret_cast<__nv_bfloat162*>(
                        o2 + (size_t)(n >> 6) * ASLAB + loc) = hh;
                    *reinterpret_cast<__nv_bfloat162*>(
                        o2 + (size_t)(4 + (n >> 6)) * ASLAB + loc) = ll;
                }
            }
        }
    }
}

// ---------------- hi/lo conversion of h (slabbed, swizzled) ----------------
__global__ void conv_h_kernel(const float* __restrict__ h) {
    int idx = blockIdx.x * 256 + threadIdx.x;
    int m = idx >> 8, e = idx & 255;
    float v = h[idx];
    __nv_bfloat16 hi = __float2bfloat16(v);
    __nv_bfloat16 lo = __float2bfloat16(v - __bfloat162float(hi));
    uint32_t loc = SWZ((uint32_t)(m * 128 + (e & 63) * 2));
    char* base = (char*)g_x2a;
    *reinterpret_cast<__nv_bfloat16*>(base + (size_t)(e >> 6) * ASLAB + loc) = hi;
    *reinterpret_cast<__nv_bfloat16*>(base + (size_t)(4 + (e >> 6)) * ASLAB + loc) = lo;
}

// ---------------- weight conversion (slabbed, swizzled) ----------------
__global__ void conv_w_kernel(const float* __restrict__ Wpre,
                              const float* __restrict__ W0,
                              const float* __restrict__ Wres) {
    int g = blockIdx.y;
    int i = blockIdx.x * 256 + threadIdx.x;  // 0..65535
    int n = i >> 8, k = i & 255;
    const float* src = (g < 2) ? (Wpre + (size_t)g * 65536)
                     : (g == 2) ? W0
                     : (Wres + (size_t)(g - 3) * 65536);
    float v = src[i];
    __nv_bfloat16 hi = __float2bfloat16(v);
    __nv_bfloat16 lo = __float2bfloat16(v - __bfloat162float(hi));
    uint32_t loc = SWZ((uint32_t)((n & 63) * 128 + (k & 63) * 2));
    char* base = (char*)g_wc + (size_t)g * 262144 + (size_t)(n >> 6) * W_PB;
    *reinterpret_cast<__nv_bfloat16*>(base + (size_t)(k >> 6) * 8192 + loc) = hi;
    *reinterpret_cast<__nv_bfloat16*>(base + (size_t)(4 + (k >> 6)) * 8192 + loc) = lo;
}

// ---------------- segment offsets from sorted batch_seg ----------------
__global__ void seg_offsets_kernel(const int* __restrict__ seg) {
    int n = blockIdx.x * blockDim.x + threadIdx.x;
    if (n >= NN) return;
    int s = seg[n];
    if (n == 0) {
        for (int b = 0; b <= s; b++) g_off[b] = 0;
    } else {
        int p = seg[n - 1];
        for (int b = p + 1; b <= s; b++) g_off[b] = n;
    }
    if (n == NN - 1) {
        for (int b = s + 1; b <= BB; b++) g_off[b] = NN;
    }
}

// ---------------- dot products + cos/sin ----------------
__global__ void dot_kernel(const float* __restrict__ x,
                           const float* __restrict__ kvec,
                           const int* __restrict__ seg,
                           float* __restrict__ dot_out) {
    int n = blockIdx.x;
    int kk = threadIdx.x;  // 128
    int b = seg[n];
    float x0 = x[n * 3 + 0], x1 = x[n * 3 + 1], x2 = x[n * 3 + 2];
    const float* kr = kvec + ((size_t)b * KK + kk) * 3;
    float d = kr[0] * x0 + kr[1] * x1 + kr[2] * x2;
    dot_out[n * KK + kk] = d;
    float cv, sv;
    sincosf(d, &sv, &cv);
    g_c[n * KK + kk] = cv;
    g_s[n * KK + kk] = sv;
}

// ---------------- low-rank k-filter ----------------
__global__ void kf_kernel(const float* __restrict__ Wup,
                          const float* __restrict__ Wdn) {
    int e = threadIdx.x;
    int k = blockIdx.x;
    float a = 0.f;
#pragma unroll
    for (int d = 0; d < DD; d++) a += Wup[e * DD + d] * Wdn[d * KK + k];
    g_kf[k * EE + e] = a;
}

// ---------------- structure factors (kfilter folded in) ----------------
__global__ void __launch_bounds__(256, 4) sf_kernel() {
    int b  = blockIdx.z;
    int k0 = blockIdx.y * 32;
    int e0 = blockIdx.x * 32;
    int t = threadIdx.x;
    int e4 = t & 7;
    int ky = t >> 3;
    __shared__ float csh[32][32], ssh[32][32], hsh[32][32];
    int st = g_off[b], en = g_off[b + 1];
    float aR[4] = {0.f, 0.f, 0.f, 0.f};
    float aI[4] = {0.f, 0.f, 0.f, 0.f};
    for (int n0 = st; n0 < en; n0 += 32) {
#pragma unroll
        for (int l = 0; l < 4; l++) {
            int idx = t + 256 * l;
            int r = idx >> 5, c = idx & 31;
            int n = n0 + r;
            bool v = (n < en);
            csh[r][c] = v ? g_c[n * KK + k0 + c] : 0.f;
            ssh[r][c] = v ? g_s[n * KK + k0 + c] : 0.f;
            hsh[r][c] = v ? g_hres[(size_t)n * EE + e0 + c] : 0.f;
        }
        __syncthreads();
#pragma unroll
        for (int nn = 0; nn < 32; nn++) {
            float4 hv = *reinterpret_cast<float4*>(&hsh[nn][e4 * 4]);
            float cv = csh[nn][ky];
            float sv = ssh[nn][ky];
            aR[0] += cv * hv.x; aR[1] += cv * hv.y; aR[2] += cv * hv.z; aR[3] += cv * hv.w;
            aI[0] += sv * hv.x; aI[1] += sv * hv.y; aI[2] += sv * hv.z; aI[3] += sv * hv.w;
        }
        __syncthreads();
    }
    float4 f = *reinterpret_cast<float4*>(&g_kf[(k0 + ky) * EE + e0 + e4 * 4]);
    size_t idx = ((size_t)b * KK + k0 + ky) * EE + e0 + e4 * 4;
    float4 oR, oI;
    oR.x = aR[0] * f.x; oR.y = aR[1] * f.y; oR.z = aR[2] * f.z; oR.w = aR[3] * f.w;
    oI.x = aI[0] * f.x; oI.y = aI[1] * f.y; oI.z = aI[2] * f.z; oI.w = aI[3] * f.w;
    *reinterpret_cast<float4*>(&g_sfr[idx]) = oR;
    *reinterpret_cast<float4*>(&g_sfi[idx]) = oI;
}

// ---------------- back-projection; writes hi/lo bf16 (slabbed) --------------
__global__ void __launch_bounds__(256, 4) hupd_kernel(const int* __restrict__ seg) {
    int n0 = blockIdx.y * 32;
    int e0 = blockIdx.x * 32;
    int t = threadIdx.x;
    int e4 = t & 7;
    int ny = t >> 3;
    int n = n0 + ny;
    int b = seg[n];
    __shared__ float csh[32][32], ssh[32][32];
    float acc[4] = {0.f, 0.f, 0.f, 0.f};
    for (int k0c = 0; k0c < KK; k0c += 32) {
#pragma unroll
        for (int l = 0; l < 4; l++) {
            int idx = t + 256 * l;
            int r = idx >> 5, c = idx & 31;
            csh[r][c] = g_c[(n0 + r) * KK + k0c + c];
            ssh[r][c] = g_s[(n0 + r) * KK + k0c + c];
        }
        __syncthreads();
        const float* baseR = g_sfr + ((size_t)b * KK + k0c) * EE + e0 + e4 * 4;
        const float* baseI = g_sfi + ((size_t)b * KK + k0c) * EE + e0 + e4 * 4;
#pragma unroll
        for (int kk = 0; kk < 32; kk++) {
            float cv = csh[ny][kk];
            float sv = ssh[ny][kk];
            float4 pr = *reinterpret_cast<const float4*>(baseR + (size_t)kk * EE);
            float4 pi = *reinterpret_cast<const float4*>(baseI + (size_t)kk * EE);
            acc[0] += cv * pr.x + sv * pi.x;
            acc[1] += cv * pr.y + sv * pi.y;
            acc[2] += cv * pr.z + sv * pi.z;
            acc[3] += cv * pr.w + sv * pi.w;
        }
        __syncthreads();
    }
    __nv_bfloat16 hi[4], lo[4];
#pragma unroll
    for (int q = 0; q < 4; q++) {
        float v = 0.01f * acc[q];
        hi[q] = __float2bfloat16(v);
        lo[q] = __float2bfloat16(v - __bfloat162float(hi[q]));
    }
    int e = e0 + e4 * 4;
    uint32_t loc = SWZ((uint32_t)(n * 128 + (e & 63) * 2));
    char* base = (char*)g_x2a;
    *reinterpret_cast<uint2*>(base + (size_t)(e >> 6) * ASLAB + loc) =
        *reinterpret_cast<uint2*>(hi);
    *reinterpret_cast<uint2*>(base + (size_t)(4 + (e >> 6)) * ASLAB + loc) =
        *reinterpret_cast<uint2*>(lo);
}

// ---------------- launch ----------------
extern "C" void kernel_launch(void* const* d_in, const int* in_sizes, int n_in,
                              void* d_out, int out_size) {
    const float *h = nullptr, *x = nullptr, *kv = nullptr;
    const float *Wpre = nullptr, *Wdn = nullptr, *Wup = nullptr;
    const float *W0 = nullptr, *Wres = nullptr;
    const int* seg = nullptr;

    for (int i = 0; i < n_in; i++) {
        switch (in_sizes[i]) {
            case NN * EE:           h    = (const float*)d_in[i]; break;
            case NN * 3:            x    = (const float*)d_in[i]; break;
            case BB * KK * 3:       kv   = (const float*)d_in[i]; break;
            case NN:                seg  = (const int*)d_in[i];   break;
            case 2 * EE * EE:       Wpre = (const float*)d_in[i]; break;
            case DD * KK:           Wdn  = (const float*)d_in[i]; break;
            case EE * DD:           Wup  = (const float*)d_in[i]; break;
            case EE * EE:           W0   = (const float*)d_in[i]; break;
            case 3 * 2 * EE * EE:   Wres = (const float*)d_in[i]; break;
            default: break;
        }
    }

    float* out = (float*)d_out;
    float* out_hu  = out;            // (NN, EE)
    float* out_dot = out + NN * EE;  // (NN, KK)

    float *t0, *hres;
    __nv_bfloat16 *x2a, *x2b, *wc;
    cudaGetSymbolAddress((void**)&t0,   g_t0);
    cudaGetSymbolAddress((void**)&hres, g_hres);
    cudaGetSymbolAddress((void**)&x2a,  g_x2a);
    cudaGetSymbolAddress((void**)&x2b,  g_x2b);
    cudaGetSymbolAddress((void**)&wc,   g_wc);

    cudaFuncSetAttribute(gemm_mma_kernel,
                         cudaFuncAttributeMaxDynamicSharedMemorySize, GEMM_SMEM);
    dim3 ggrid(EE / 64, NN / 128);  // (4, 32) = 128 CTAs

    // conversions
    conv_w_kernel<<<dim3(256, 9), 256>>>(Wpre, W0, Wres);
    conv_h_kernel<<<NN * EE / 256, 256>>>(h);

    // pre-residual: x2b = silu(h@W0'), hres = h + silu(x2b@W1')
    gemm_mma_kernel<<<ggrid, 512, GEMM_SMEM>>>(x2a, wc + 0 * 131072, nullptr, nullptr, x2b);
    gemm_mma_kernel<<<ggrid, 512, GEMM_SMEM>>>(x2b, wc + 1 * 131072, h, hres, nullptr);

    // Ewald geometry path
    seg_offsets_kernel<<<(NN + 255) / 256, 256>>>(seg);
    dot_kernel<<<NN, KK>>>(x, kv, seg, out_dot);
    kf_kernel<<<KK, EE>>>(Wup, Wdn);
    sf_kernel<<<dim3(EE / 32, KK / 32, BB), 256>>>();
    hupd_kernel<<<dim3(EE / 32, NN / 32), 256>>>(seg);  // -> g_x2a (slabbed hi/lo)

    // update MLP: t0 = silu(hu @ W0^T)
    gemm_mma_kernel<<<ggrid, 512, GEMM_SMEM>>>(x2a, wc + 2 * 131072, nullptr, t0, x2b);

    // 3 residual blocks
    for (int i = 0; i < 3; i++) {
        const __nv_bfloat16* wa = wc + (size_t)(3 + 2 * i) * 131072;
        const __nv_bfloat16* wb = wc + (size_t)(4 + 2 * i) * 131072;
        gemm_mma_kernel<<<ggrid, 512, GEMM_SMEM>>>(x2b, wa, nullptr, nullptr, x2a);
        float* dstf = (i == 2) ? out_hu : t0;
        __nv_bfloat16* dst2 = (i == 2) ? nullptr : x2b;
        gemm_mma_kernel<<<ggrid, 512, GEMM_SMEM>>>(x2a, wb, t0, dstf, dst2);
    }
}

// round 8
// speedup vs baseline: 2.8909x; 1.0317x over previous
#include <cuda_runtime.h>
#include <cuda_bf16.h>
#include <math.h>
#include <stdint.h>

// Problem constants (fixed shapes per reference)
#define NN 4096
#define EE 256
#define KK 128
#define BB 64
#define DD 8

// ---------------- scratch (no allocations allowed) ----------------
__device__ float g_t0[NN * EE];
__device__ float g_hres[NN * EE];
__device__ float g_c[NN * KK];
__device__ float g_s[NN * KK];
__device__ float g_sfr[BB * KK * EE];
__device__ float g_sfi[BB * KK * EE];
__device__ float g_kf[KK * EE];
__device__ int   g_off[BB + 1];
// Activations, SLAB layout: 8 slabs [c][4096 rows][64 bf16 = 128B], SW128-swizzled.
// slabs 0-3 = hi cols 0..255, slabs 4-7 = lo cols 0..255.
__device__ __align__(128) __nv_bfloat16 g_x2a[NN * 512];
__device__ __align__(128) __nv_bfloat16 g_x2b[NN * 512];
// Weights, SLAB layout: 9 gemms x [nblk 4][c 8][64 rows][64 bf16], swizzled.
// c 0-3 = Whi, c 4-7 = Wlo.
__device__ __align__(128) __nv_bfloat16 g_wc[9 * 256 * 512];

// ---------------- helpers ----------------
__device__ __forceinline__ float silu(float v) {
    return v / (1.0f + __expf(-v));
}

__device__ __forceinline__ uint32_t smem_u32(const void* p) {
    uint32_t a;
    asm("{ .reg .u64 t; cvta.to.shared.u64 t, %1; cvt.u32.u64 %0, t; }" : "=r"(a) : "l"(p));
    return a;
}

#define SWZ(o) ((o) ^ (((o) >> 3) & 0x70))

#define LDMATRIX_X4(r0, r1, r2, r3, addr) \
    asm volatile("ldmatrix.sync.aligned.m8n8.x4.shared.b16 {%0,%1,%2,%3}, [%4];" \
                 : "=r"(r0), "=r"(r1), "=r"(r2), "=r"(r3) : "r"(addr))

#define MMA_BF16(c, a, b0, b1) \
    asm volatile("mma.sync.aligned.m16n8k16.row.col.f32.bf16.bf16.f32 " \
                 "{%0,%1,%2,%3},{%4,%5,%6,%7},{%8,%9},{%0,%1,%2,%3};" \
                 : "+f"((c)[0]), "+f"((c)[1]), "+f"((c)[2]), "+f"((c)[3]) \
                 : "r"((a)[0]), "r"((a)[1]), "r"((a)[2]), "r"((a)[3]), \
                   "r"(b0), "r"(b1))

#define MBAR_INIT(a, c) \
    asm volatile("mbarrier.init.shared.b64 [%0], %1;" :: "r"(a), "r"((uint32_t)(c)) : "memory")

#define MBAR_EXPECT_TX(a, n) \
    asm volatile("mbarrier.arrive.expect_tx.shared.b64 _, [%0], %1;" \
                 :: "r"(a), "r"((uint32_t)(n)) : "memory")

#define MBAR_WAIT(addr, ph) do { \
    uint32_t _m = (addr), _p = (uint32_t)(ph), _d; \
    asm volatile("{\n\t.reg .pred p;\n\tmbarrier.try_wait.parity.acquire.cta.shared::cta.b64 p, [%1], %2;\n\tselp.b32 %0, 1, 0, p;\n\t}" \
        : "=r"(_d) : "r"(_m), "r"(_p) : "memory"); \
    if (!_d) { \
        asm volatile("{\n\t.reg .pred P1;\n\tWL_%=:\n\tmbarrier.try_wait.parity.acquire.cta.shared::cta.b64 P1, [%0], %1, 0x989680;\n\t@P1 bra.uni WD_%=;\n\tbra.uni WL_%=;\n\tWD_%=:\n\t}" \
            :: "r"(_m), "r"(_p) : "memory"); \
    } \
} while (0)

#define CP_BULK(dst, src, bytes, mbar) \
    asm volatile("cp.async.bulk.shared::cta.global.mbarrier::complete_tx::bytes " \
                 "[%0], [%1], %2, [%3];" \
                 :: "r"(dst), "l"(src), "r"((uint32_t)(bytes)), "r"(mbar) : "memory")

// ============================================================================
// HMMA GEMM, W-persistent, bulk-copy loads: out = silu(A @ W^T) [+ skip]
// A2: slabbed (8 x [4096][128B], swizzled).  Wc: slabbed per-nblk 64KB.
// 3-term split: Ahi*Whi + Ahi*Wlo + Alo*Whi.
// CTA tile 128x64, 512 threads = 16 warps (4m x 4n), warp tile 32x16.
// W slice: ONE 64KB cp.async.bulk. A: 8 x 16KB bulk through 3-stage ring,
// issued one full chunk ahead. kh-fragments explicitly double-buffered.
// ============================================================================
#define ASLAB (4096 * 128)          // bytes per activation slab (512KB)
#define A_ST  16384                  // A stage bytes (128 rows x 128B)
#define W_PB  65536                  // W persistent bytes (8 slabs x 8KB)
#define GEMM_SMEM (W_PB + 3 * A_ST)  // 114688

__global__ void __launch_bounds__(512, 1) gemm_mma_kernel(
    const __nv_bfloat16* __restrict__ A2,
    const __nv_bfloat16* __restrict__ Wc,   // already offset to this gemm
    const float* __restrict__ skip,
    float* __restrict__ outf,
    __nv_bfloat16* __restrict__ out2)
{
    extern __shared__ char smem[];
    uint32_t sb = smem_u32(smem);            // [0,65536): W; then 3 A stages
    __shared__ __align__(8) uint64_t mbars[4];  // 0-2: A stages, 3: W

    int tid = threadIdx.x, wid = tid >> 5, lane = tid & 31;
    int m0 = blockIdx.y * 128, n0 = blockIdx.x * 64;
    int nb = blockIdx.x;
    int warp_m = (wid & 3) * 32, warp_n = (wid >> 2) * 16;

    uint32_t mb[3] = { smem_u32(&mbars[0]), smem_u32(&mbars[1]), smem_u32(&mbars[2]) };
    uint32_t wbar  = smem_u32(&mbars[3]);

    if (tid == 0) {
        MBAR_INIT(mb[0], 1);
        MBAR_INIT(mb[1], 1);
        MBAR_INIT(mb[2], 1);
        MBAR_INIT(wbar, 1);
    }
    __syncthreads();

    const char* gA = (const char*)A2 + (size_t)m0 * 128;   // + c*ASLAB per chunk
    const char* gW = (const char*)Wc + (size_t)nb * W_PB;

    if (tid == 0) {
        MBAR_EXPECT_TX(wbar, W_PB);
        CP_BULK(sb, gW, W_PB, wbar);
        MBAR_EXPECT_TX(mb[0], A_ST);
        CP_BULK(sb + W_PB, gA + 0 * (size_t)ASLAB, A_ST, mb[0]);
        MBAR_EXPECT_TX(mb[1], A_ST);
        CP_BULK(sb + W_PB + A_ST, gA + 1 * (size_t)ASLAB, A_ST, mb[1]);
    }

    float acc[2][2][4];
#pragma unroll
    for (int i = 0; i < 2; i++)
#pragma unroll
        for (int j = 0; j < 2; j++)
#pragma unroll
            for (int q = 0; q < 4; q++) acc[i][j][q] = 0.f;

    // precomputed intra-stage LDSM address offsets (swizzled per kh)
    int arow0 = warp_m + (lane & 15);
    int brow  = warp_n + (lane & 15);
    int hi16  = (lane >> 4) * 16;

    MBAR_WAIT(wbar, 0);

#pragma unroll
    for (int ch = 0; ch < 8; ch++) {
        // issue A chunk ch+2 FIRST: its stage ((ch+2)%3) was consumed at chunk
        // ch-1, whose trailing __syncthreads already protects it.
        if (ch + 2 < 8 && tid == 0) {
            int ns = (ch + 2) % 3;
            MBAR_EXPECT_TX(mb[ns], A_ST);
            CP_BULK(sb + W_PB + ns * A_ST, gA + (size_t)(ch + 2) * ASLAB, A_ST, mb[ns]);
        }

        const int s = ch % 3;
        MBAR_WAIT(mb[s], (ch / 3) & 1);

        uint32_t aB = sb + W_PB + s * A_ST;
        const bool isHi = (ch < 4);
        const uint32_t whiB = sb + (uint32_t)((isHi ? ch : (ch - 4)) * 8192);
        const uint32_t wloB = sb + (uint32_t)((4 + ch) * 8192);

        // fragment double-buffering over kh
        uint32_t a[2][2][4], bh[2][4], bl[2][4];

        // prologue: load kh=0 fragments into buf 0
        {
            uint32_t o0 = SWZ((uint32_t)(arow0 * 128 + hi16));
            uint32_t o1 = SWZ((uint32_t)((arow0 + 16) * 128 + hi16));
            LDMATRIX_X4(a[0][0][0], a[0][0][1], a[0][0][2], a[0][0][3], aB + o0);
            LDMATRIX_X4(a[0][1][0], a[0][1][1], a[0][1][2], a[0][1][3], aB + o1);
            uint32_t bo = SWZ((uint32_t)(brow * 128 + hi16));
            LDMATRIX_X4(bh[0][0], bh[0][1], bh[0][2], bh[0][3], whiB + bo);
            if (isHi) LDMATRIX_X4(bl[0][0], bl[0][1], bl[0][2], bl[0][3], wloB + bo);
        }

#pragma unroll
        for (int kh = 0; kh < 4; kh++) {
            const int cur = kh & 1, nxt = cur ^ 1;
            if (kh < 3) {
                uint32_t ko = (uint32_t)((kh + 1) * 32 + hi16);
                uint32_t o0 = SWZ((uint32_t)(arow0 * 128) + ko);
                uint32_t o1 = SWZ((uint32_t)((arow0 + 16) * 128) + ko);
                LDMATRIX_X4(a[nxt][0][0], a[nxt][0][1], a[nxt][0][2], a[nxt][0][3], aB + o0);
                LDMATRIX_X4(a[nxt][1][0], a[nxt][1][1], a[nxt][1][2], a[nxt][1][3], aB + o1);
                uint32_t bo = SWZ((uint32_t)(brow * 128) + ko);
                LDMATRIX_X4(bh[nxt][0], bh[nxt][1], bh[nxt][2], bh[nxt][3], whiB + bo);
                if (isHi) LDMATRIX_X4(bl[nxt][0], bl[nxt][1], bl[nxt][2], bl[nxt][3], wloB + bo);
            }
#pragma unroll
            for (int mt = 0; mt < 2; mt++)
#pragma unroll
                for (int j = 0; j < 2; j++)
                    MMA_BF16(acc[mt][j], a[cur][mt], bh[cur][j], bh[cur][j + 2]);
            if (isHi) {
#pragma unroll
                for (int mt = 0; mt < 2; mt++)
#pragma unroll
                    for (int j = 0; j < 2; j++)
                        MMA_BF16(acc[mt][j], a[cur][mt], bl[cur][j], bl[cur][j + 2]);
            }
        }

        __syncthreads();
    }

    // ---------------- epilogue ----------------
    char* o2 = (char*)out2;
    int r0 = lane >> 2, cp = (lane & 3) * 2;
#pragma unroll
    for (int mt = 0; mt < 2; mt++) {
#pragma unroll
        for (int j = 0; j < 2; j++) {
            int n = n0 + warp_n + j * 8 + cp;
#pragma unroll
            for (int half = 0; half < 2; half++) {
                int m = m0 + warp_m + mt * 16 + r0 + half * 8;
                float v0 = acc[mt][j][half * 2 + 0];
                float v1 = acc[mt][j][half * 2 + 1];
                v0 = silu(v0);
                v1 = silu(v1);
                if (skip) {
                    float2 sk = *reinterpret_cast<const float2*>(skip + (size_t)m * 256 + n);
                    v0 += sk.x; v1 += sk.y;
                }
                if (outf) {
                    float2 o; o.x = v0; o.y = v1;
                    *reinterpret_cast<float2*>(outf + (size_t)m * 256 + n) = o;
                }
                if (out2) {
                    __nv_bfloat16 h0 = __float2bfloat16(v0);
                    __nv_bfloat16 h1 = __float2bfloat16(v1);
                    __nv_bfloat162 hh; hh.x = h0; hh.y = h1;
                    __nv_bfloat162 ll;
                    ll.x = __float2bfloat16(v0 - __bfloat162float(h0));
                    ll.y = __float2bfloat16(v1 - __bfloat162float(h1));
                    uint32_t loc = SWZ((uint32_t)(m * 128 + (n & 63) * 2));
                    *reinterpret_cast<__nv_bfloat162*>(
                        o2 + (size_t)(n >> 6) * ASLAB + loc) = hh;
                    *reinterpret_cast<__nv_bfloat162*>(
                        o2 + (size_t)(4 + (n >> 6)) * ASLAB + loc) = ll;
                }
            }
        }
    }
}

// ---------------- hi/lo conversion of h (slabbed, swizzled) ----------------
__global__ void conv_h_kernel(const float* __restrict__ h) {
    int idx = blockIdx.x * 256 + threadIdx.x;
    int m = idx >> 8, e = idx & 255;
    float v = h[idx];
    __nv_bfloat16 hi = __float2bfloat16(v);
    __nv_bfloat16 lo = __float2bfloat16(v - __bfloat162float(hi));
    uint32_t loc = SWZ((uint32_t)(m * 128 + (e & 63) * 2));
    char* base = (char*)g_x2a;
    *reinterpret_cast<__nv_bfloat16*>(base + (size_t)(e >> 6) * ASLAB + loc) = hi;
    *reinterpret_cast<__nv_bfloat16*>(base + (size_t)(4 + (e >> 6)) * ASLAB + loc) = lo;
}

// ---------------- weight conversion (slabbed, swizzled) ----------------
__global__ void conv_w_kernel(const float* __restrict__ Wpre,
                              const float* __restrict__ W0,
                              const float* __restrict__ Wres) {
    int g = blockIdx.y;
    int i = blockIdx.x * 256 + threadIdx.x;  // 0..65535
    int n = i >> 8, k = i & 255;
    const float* src = (g < 2) ? (Wpre + (size_t)g * 65536)
                     : (g == 2) ? W0
                     : (Wres + (size_t)(g - 3) * 65536);
    float v = src[i];
    __nv_bfloat16 hi = __float2bfloat16(v);
    __nv_bfloat16 lo = __float2bfloat16(v - __bfloat162float(hi));
    uint32_t loc = SWZ((uint32_t)((n & 63) * 128 + (k & 63) * 2));
    char* base = (char*)g_wc + (size_t)g * 262144 + (size_t)(n >> 6) * W_PB;
    *reinterpret_cast<__nv_bfloat16*>(base + (size_t)(k >> 6) * 8192 + loc) = hi;
    *reinterpret_cast<__nv_bfloat16*>(base + (size_t)(4 + (k >> 6)) * 8192 + loc) = lo;
}

// ---------------- segment offsets from sorted batch_seg ----------------
__global__ void seg_offsets_kernel(const int* __restrict__ seg) {
    int n = blockIdx.x * blockDim.x + threadIdx.x;
    if (n >= NN) return;
    int s = seg[n];
    if (n == 0) {
        for (int b = 0; b <= s; b++) g_off[b] = 0;
    } else {
        int p = seg[n - 1];
        for (int b = p + 1; b <= s; b++) g_off[b] = n;
    }
    if (n == NN - 1) {
        for (int b = s + 1; b <= BB; b++) g_off[b] = NN;
    }
}

// ---------------- dot products + cos/sin ----------------
__global__ void dot_kernel(const float* __restrict__ x,
                           const float* __restrict__ kvec,
                           const int* __restrict__ seg,
                           float* __restrict__ dot_out) {
    int n = blockIdx.x;
    int kk = threadIdx.x;  // 128
    int b = seg[n];
    float x0 = x[n * 3 + 0], x1 = x[n * 3 + 1], x2 = x[n * 3 + 2];
    const float* kr = kvec + ((size_t)b * KK + kk) * 3;
    float d = kr[0] * x0 + kr[1] * x1 + kr[2] * x2;
    dot_out[n * KK + kk] = d;
    float cv, sv;
    sincosf(d, &sv, &cv);
    g_c[n * KK + kk] = cv;
    g_s[n * KK + kk] = sv;
}

// ---------------- low-rank k-filter ----------------
__global__ void kf_kernel(const float* __restrict__ Wup,
                          const float* __restrict__ Wdn) {
    int e = threadIdx.x;
    int k = blockIdx.x;
    float a = 0.f;
#pragma unroll
    for (int d = 0; d < DD; d++) a += Wup[e * DD + d] * Wdn[d * KK + k];
    g_kf[k * EE + e] = a;
}

// ---------------- structure factors (kfilter folded in) ----------------
__global__ void __launch_bounds__(256, 4) sf_kernel() {
    int b  = blockIdx.z;
    int k0 = blockIdx.y * 32;
    int e0 = blockIdx.x * 32;
    int t = threadIdx.x;
    int e4 = t & 7;
    int ky = t >> 3;
    __shared__ float csh[32][32], ssh[32][32], hsh[32][32];
    int st = g_off[b], en = g_off[b + 1];
    float aR[4] = {0.f, 0.f, 0.f, 0.f};
    float aI[4] = {0.f, 0.f, 0.f, 0.f};
    for (int n0 = st; n0 < en; n0 += 32) {
#pragma unroll
        for (int l = 0; l < 4; l++) {
            int idx = t + 256 * l;
            int r = idx >> 5, c = idx & 31;
            int n = n0 + r;
            bool v = (n < en);
            csh[r][c] = v ? g_c[n * KK + k0 + c] : 0.f;
            ssh[r][c] = v ? g_s[n * KK + k0 + c] : 0.f;
            hsh[r][c] = v ? g_hres[(size_t)n * EE + e0 + c] : 0.f;
        }
        __syncthreads();
#pragma unroll
        for (int nn = 0; nn < 32; nn++) {
            float4 hv = *reinterpret_cast<float4*>(&hsh[nn][e4 * 4]);
            float cv = csh[nn][ky];
            float sv = ssh[nn][ky];
            aR[0] += cv * hv.x; aR[1] += cv * hv.y; aR[2] += cv * hv.z; aR[3] += cv * hv.w;
            aI[0] += sv * hv.x; aI[1] += sv * hv.y; aI[2] += sv * hv.z; aI[3] += sv * hv.w;
        }
        __syncthreads();
    }
    float4 f = *reinterpret_cast<float4*>(&g_kf[(k0 + ky) * EE + e0 + e4 * 4]);
    size_t idx = ((size_t)b * KK + k0 + ky) * EE + e0 + e4 * 4;
    float4 oR, oI;
    oR.x = aR[0] * f.x; oR.y = aR[1] * f.y; oR.z = aR[2] * f.z; oR.w = aR[3] * f.w;
    oI.x = aI[0] * f.x; oI.y = aI[1] * f.y; oI.z = aI[2] * f.z; oI.w = aI[3] * f.w;
    *reinterpret_cast<float4*>(&g_sfr[idx]) = oR;
    *reinterpret_cast<float4*>(&g_sfi[idx]) = oI;
}

// ---------------- back-projection; writes hi/lo bf16 (slabbed) --------------
__global__ void __launch_bounds__(256, 4) hupd_kernel(const int* __restrict__ seg) {
    int n0 = blockIdx.y * 32;
    int e0 = blockIdx.x * 32;
    int t = threadIdx.x;
    int e4 = t & 7;
    int ny = t >> 3;
    int n = n0 + ny;
    int b = seg[n];
    __shared__ float csh[32][32], ssh[32][32];
    float acc[4] = {0.f, 0.f, 0.f, 0.f};
    for (int k0c = 0; k0c < KK; k0c += 32) {
#pragma unroll
        for (int l = 0; l < 4; l++) {
            int idx = t + 256 * l;
            int r = idx >> 5, c = idx & 31;
            csh[r][c] = g_c[(n0 + r) * KK + k0c + c];
            ssh[r][c] = g_s[(n0 + r) * KK + k0c + c];
        }
        __syncthreads();
        const float* baseR = g_sfr + ((size_t)b * KK + k0c) * EE + e0 + e4 * 4;
        const float* baseI = g_sfi + ((size_t)b * KK + k0c) * EE + e0 + e4 * 4;
#pragma unroll
        for (int kk = 0; kk < 32; kk++) {
            float cv = csh[ny][kk];
            float sv = ssh[ny][kk];
            float4 pr = *reinterpret_cast<const float4*>(baseR + (size_t)kk * EE);
            float4 pi = *reinterpret_cast<const float4*>(baseI + (size_t)kk * EE);
            acc[0] += cv * pr.x + sv * pi.x;
            acc[1] += cv * pr.y + sv * pi.y;
            acc[2] += cv * pr.z + sv * pi.z;
            acc[3] += cv * pr.w + sv * pi.w;
        }
        __syncthreads();
    }
    __nv_bfloat16 hi[4], lo[4];
#pragma unroll
    for (int q = 0; q < 4; q++) {
        float v = 0.01f * acc[q];
        hi[q] = __float2bfloat16(v);
        lo[q] = __float2bfloat16(v - __bfloat162float(hi[q]));
    }
    int e = e0 + e4 * 4;
    uint32_t loc = SWZ((uint32_t)(n * 128 + (e & 63) * 2));
    char* base = (char*)g_x2a;
    *reinterpret_cast<uint2*>(base + (size_t)(e >> 6) * ASLAB + loc) =
        *reinterpret_cast<uint2*>(hi);
    *reinterpret_cast<uint2*>(base + (size_t)(4 + (e >> 6)) * ASLAB + loc) =
        *reinterpret_cast<uint2*>(lo);
}

// ---------------- launch ----------------
extern "C" void kernel_launch(void* const* d_in, const int* in_sizes, int n_in,
                              void* d_out, int out_size) {
    const float *h = nullptr, *x = nullptr, *kv = nullptr;
    const float *Wpre = nullptr, *Wdn = nullptr, *Wup = nullptr;
    const float *W0 = nullptr, *Wres = nullptr;
    const int* seg = nullptr;

    for (int i = 0; i < n_in; i++) {
        switch (in_sizes[i]) {
            case NN * EE:           h    = (const float*)d_in[i]; break;
            case NN * 3:            x    = (const float*)d_in[i]; break;
            case BB * KK * 3:       kv   = (const float*)d_in[i]; break;
            case NN:                seg  = (const int*)d_in[i];   break;
            case 2 * EE * EE:       Wpre = (const float*)d_in[i]; break;
            case DD * KK:           Wdn  = (const float*)d_in[i]; break;
            case EE * DD:           Wup  = (const float*)d_in[i]; break;
            case EE * EE:           W0   = (const float*)d_in[i]; break;
            case 3 * 2 * EE * EE:   Wres = (const float*)d_in[i]; break;
            default: break;
        }
    }

    float* out = (float*)d_out;
    float* out_hu  = out;            // (NN, EE)
    float* out_dot = out + NN * EE;  // (NN, KK)

    float *t0, *hres;
    __nv_bfloat16 *x2a, *x2b, *wc;
    cudaGetSymbolAddress((void**)&t0,   g_t0);
    cudaGetSymbolAddress((void**)&hres, g_hres);
    cudaGetSymbolAddress((void**)&x2a,  g_x2a);
    cudaGetSymbolAddress((void**)&x2b,  g_x2b);
    cudaGetSymbolAddress((void**)&wc,   g_wc);

    cudaFuncSetAttribute(gemm_mma_kernel,
                         cudaFuncAttributeMaxDynamicSharedMemorySize, GEMM_SMEM);
    dim3 ggrid(EE / 64, NN / 128);  // (4, 32) = 128 CTAs

    // conversions
    conv_w_kernel<<<dim3(256, 9), 256>>>(Wpre, W0, Wres);
    conv_h_kernel<<<NN * EE / 256, 256>>>(h);

    // pre-residual: x2b = silu(h@W0'), hres = h + silu(x2b@W1')
    gemm_mma_kernel<<<ggrid, 512, GEMM_SMEM>>>(x2a, wc + 0 * 131072, nullptr, nullptr, x2b);
    gemm_mma_kernel<<<ggrid, 512, GEMM_SMEM>>>(x2b, wc + 1 * 131072, h, hres, nullptr);

    // Ewald geometry path
    seg_offsets_kernel<<<(NN + 255) / 256, 256>>>(seg);
    dot_kernel<<<NN, KK>>>(x, kv, seg, out_dot);
    kf_kernel<<<KK, EE>>>(Wup, Wdn);
    sf_kernel<<<dim3(EE / 32, KK / 32, BB), 256>>>();
    hupd_kernel<<<dim3(EE / 32, NN / 32), 256>>>(seg);  // -> g_x2a (slabbed hi/lo)

    // update MLP: t0 = silu(hu @ W0^T)
    gemm_mma_kernel<<<ggrid, 512, GEMM_SMEM>>>(x2a, wc + 2 * 131072, nullptr, t0, x2b);

    // 3 residual blocks
    for (int i = 0; i < 3; i++) {
        const __nv_bfloat16* wa = wc + (size_t)(3 + 2 * i) * 131072;
        const __nv_bfloat16* wb = wc + (size_t)(4 + 2 * i) * 131072;
        gemm_mma_kernel<<<ggrid, 512, GEMM_SMEM>>>(x2b, wa, nullptr, nullptr, x2a);
        float* dstf = (i == 2) ? out_hu : t0;
        __nv_bfloat16* dst2 = (i == 2) ? nullptr : x2b;
        gemm_mma_kernel<<<ggrid, 512, GEMM_SMEM>>>(x2a, wb, t0, dstf, dst2);
    }
}

// round 9
// speedup vs baseline: 2.9241x; 1.0115x over previous
#include <cuda_runtime.h>
#include <cuda_bf16.h>
#include <math.h>
#include <stdint.h>

// Problem constants (fixed shapes per reference)
#define NN 4096
#define EE 256
#define KK 128
#define BB 64
#define DD 8

// ---------------- scratch (no allocations allowed) ----------------
__device__ float g_t0[NN * EE];
__device__ float g_hres[NN * EE];
__device__ float g_c[NN * KK];
__device__ float g_s[NN * KK];
__device__ float g_sfr[BB * KK * EE];
__device__ float g_sfi[BB * KK * EE];
__device__ float g_kf[KK * EE];
__device__ int   g_off[BB + 1];
// Activations, SLAB layout: 8 slabs [c][4096 rows][64 bf16 = 128B], SW128-swizzled.
// slabs 0-3 = hi cols 0..255, slabs 4-7 = lo cols 0..255.
__device__ __align__(128) __nv_bfloat16 g_x2a[NN * 512];
__device__ __align__(128) __nv_bfloat16 g_x2b[NN * 512];
// Weights, SLAB layout: 9 gemms x [nblk 4][c 8][64 rows][64 bf16], swizzled.
// c 0-3 = Whi, c 4-7 = Wlo.
__device__ __align__(128) __nv_bfloat16 g_wc[9 * 256 * 512];

// ---------------- helpers ----------------
__device__ __forceinline__ float silu(float v) {
    return v / (1.0f + __expf(-v));
}

__device__ __forceinline__ uint32_t smem_u32(const void* p) {
    uint32_t a;
    asm("{ .reg .u64 t; cvta.to.shared.u64 t, %1; cvt.u32.u64 %0, t; }" : "=r"(a) : "l"(p));
    return a;
}

#define SWZ(o) ((o) ^ (((o) >> 3) & 0x70))

#define LDMATRIX_X4(r0, r1, r2, r3, addr) \
    asm volatile("ldmatrix.sync.aligned.m8n8.x4.shared.b16 {%0,%1,%2,%3}, [%4];" \
                 : "=r"(r0), "=r"(r1), "=r"(r2), "=r"(r3) : "r"(addr))

#define MMA_BF16(c, a, b0, b1) \
    asm volatile("mma.sync.aligned.m16n8k16.row.col.f32.bf16.bf16.f32 " \
                 "{%0,%1,%2,%3},{%4,%5,%6,%7},{%8,%9},{%0,%1,%2,%3};" \
                 : "+f"((c)[0]), "+f"((c)[1]), "+f"((c)[2]), "+f"((c)[3]) \
                 : "r"((a)[0]), "r"((a)[1]), "r"((a)[2]), "r"((a)[3]), \
                   "r"(b0), "r"(b1))

#define MBAR_INIT(a, c) \
    asm volatile("mbarrier.init.shared.b64 [%0], %1;" :: "r"(a), "r"((uint32_t)(c)) : "memory")

#define MBAR_EXPECT_TX(a, n) \
    asm volatile("mbarrier.arrive.expect_tx.shared.b64 _, [%0], %1;" \
                 :: "r"(a), "r"((uint32_t)(n)) : "memory")

#define MBAR_WAIT(addr, ph) do { \
    uint32_t _m = (addr), _p = (uint32_t)(ph), _d; \
    asm volatile("{\n\t.reg .pred p;\n\tmbarrier.try_wait.parity.acquire.cta.shared::cta.b64 p, [%1], %2;\n\tselp.b32 %0, 1, 0, p;\n\t}" \
        : "=r"(_d) : "r"(_m), "r"(_p) : "memory"); \
    if (!_d) { \
        asm volatile("{\n\t.reg .pred P1;\n\tWL_%=:\n\tmbarrier.try_wait.parity.acquire.cta.shared::cta.b64 P1, [%0], %1, 0x989680;\n\t@P1 bra.uni WD_%=;\n\tbra.uni WL_%=;\n\tWD_%=:\n\t}" \
            :: "r"(_m), "r"(_p) : "memory"); \
    } \
} while (0)

#define CP_BULK(dst, src, bytes, mbar) \
    asm volatile("cp.async.bulk.shared::cta.global.mbarrier::complete_tx::bytes " \
                 "[%0], [%1], %2, [%3];" \
                 :: "r"(dst), "l"(src), "r"((uint32_t)(bytes)), "r"(mbar) : "memory")

// ============================================================================
// HMMA GEMM, W-persistent, bulk-copy loads: out = silu(A @ W^T) [+ skip]
// A2: slabbed (8 x [4096][128B], swizzled).  Wc: slabbed per-nblk 64KB.
// 3-term split: Ahi*Whi + Ahi*Wlo + Alo*Whi.
// CTA tile 64x64, 256 threads = 8 warps (2m x 4n), warp tile 32x16.
// Grid 256 CTAs -> 2 CTAs/SM co-resident (independent barrier domains
// overlap each other's mbarrier/sync/epilogue stalls).
// W slice: ONE 64KB cp.async.bulk. A: 8 x 8KB bulk through 3-stage ring.
// ============================================================================
#define ASLAB (4096 * 128)          // bytes per activation slab (512KB)
#define A_ST  8192                   // A stage bytes (64 rows x 128B)
#define W_PB  65536                  // W persistent bytes (8 slabs x 8KB)
#define GEMM_SMEM (W_PB + 3 * A_ST)  // 90112 -> 2 CTAs/SM

__global__ void __launch_bounds__(256, 2) gemm_mma_kernel(
    const __nv_bfloat16* __restrict__ A2,
    const __nv_bfloat16* __restrict__ Wc,   // already offset to this gemm
    const float* __restrict__ skip,
    float* __restrict__ outf,
    __nv_bfloat16* __restrict__ out2)
{
    extern __shared__ char smem[];
    uint32_t sb = smem_u32(smem);            // [0,65536): W; then 3 A stages
    __shared__ __align__(8) uint64_t mbars[4];  // 0-2: A stages, 3: W

    int tid = threadIdx.x, wid = tid >> 5, lane = tid & 31;
    int m0 = blockIdx.y * 64, n0 = blockIdx.x * 64;
    int nb = blockIdx.x;
    int warp_m = (wid & 1) * 32, warp_n = (wid >> 1) * 16;

    uint32_t mb[3] = { smem_u32(&mbars[0]), smem_u32(&mbars[1]), smem_u32(&mbars[2]) };
    uint32_t wbar  = smem_u32(&mbars[3]);

    if (tid == 0) {
        MBAR_INIT(mb[0], 1);
        MBAR_INIT(mb[1], 1);
        MBAR_INIT(mb[2], 1);
        MBAR_INIT(wbar, 1);
    }
    __syncthreads();

    const char* gA = (const char*)A2 + (size_t)m0 * 128;   // + c*ASLAB per chunk
    const char* gW = (const char*)Wc + (size_t)nb * W_PB;

    if (tid == 0) {
        MBAR_EXPECT_TX(wbar, W_PB);
        CP_BULK(sb, gW, W_PB, wbar);
        MBAR_EXPECT_TX(mb[0], A_ST);
        CP_BULK(sb + W_PB, gA + 0 * (size_t)ASLAB, A_ST, mb[0]);
        MBAR_EXPECT_TX(mb[1], A_ST);
        CP_BULK(sb + W_PB + A_ST, gA + 1 * (size_t)ASLAB, A_ST, mb[1]);
    }

    float acc[2][2][4];
#pragma unroll
    for (int i = 0; i < 2; i++)
#pragma unroll
        for (int j = 0; j < 2; j++)
#pragma unroll
            for (int q = 0; q < 4; q++) acc[i][j][q] = 0.f;

    int arow0 = warp_m + (lane & 15);
    int brow  = warp_n + (lane & 15);
    int hi16  = (lane >> 4) * 16;

    MBAR_WAIT(wbar, 0);

#pragma unroll
    for (int ch = 0; ch < 8; ch++) {
        // issue A chunk ch+2 first; its stage was consumed at chunk ch-1,
        // protected by that chunk's trailing __syncthreads.
        if (ch + 2 < 8 && tid == 0) {
            int ns = (ch + 2) % 3;
            MBAR_EXPECT_TX(mb[ns], A_ST);
            CP_BULK(sb + W_PB + ns * A_ST, gA + (size_t)(ch + 2) * ASLAB, A_ST, mb[ns]);
        }

        const int s = ch % 3;
        MBAR_WAIT(mb[s], (ch / 3) & 1);

        uint32_t aB = sb + W_PB + s * A_ST;
        const bool isHi = (ch < 4);
        const uint32_t whiB = sb + (uint32_t)((isHi ? ch : (ch - 4)) * 8192);
        const uint32_t wloB = sb + (uint32_t)((4 + ch) * 8192);

        // fragment double-buffering over kh
        uint32_t a[2][2][4], bh[2][4], bl[2][4];
        {
            uint32_t o0 = SWZ((uint32_t)(arow0 * 128 + hi16));
            uint32_t o1 = SWZ((uint32_t)((arow0 + 16) * 128 + hi16));
            LDMATRIX_X4(a[0][0][0], a[0][0][1], a[0][0][2], a[0][0][3], aB + o0);
            LDMATRIX_X4(a[0][1][0], a[0][1][1], a[0][1][2], a[0][1][3], aB + o1);
            uint32_t bo = SWZ((uint32_t)(brow * 128 + hi16));
            LDMATRIX_X4(bh[0][0], bh[0][1], bh[0][2], bh[0][3], whiB + bo);
            if (isHi) LDMATRIX_X4(bl[0][0], bl[0][1], bl[0][2], bl[0][3], wloB + bo);
        }

#pragma unroll
        for (int kh = 0; kh < 4; kh++) {
            const int cur = kh & 1, nxt = cur ^ 1;
            if (kh < 3) {
                uint32_t ko = (uint32_t)((kh + 1) * 32 + hi16);
                uint32_t o0 = SWZ((uint32_t)(arow0 * 128) + ko);
                uint32_t o1 = SWZ((uint32_t)((arow0 + 16) * 128) + ko);
                LDMATRIX_X4(a[nxt][0][0], a[nxt][0][1], a[nxt][0][2], a[nxt][0][3], aB + o0);
                LDMATRIX_X4(a[nxt][1][0], a[nxt][1][1], a[nxt][1][2], a[nxt][1][3], aB + o1);
                uint32_t bo = SWZ((uint32_t)(brow * 128) + ko);
                LDMATRIX_X4(bh[nxt][0], bh[nxt][1], bh[nxt][2], bh[nxt][3], whiB + bo);
                if (isHi) LDMATRIX_X4(bl[nxt][0], bl[nxt][1], bl[nxt][2], bl[nxt][3], wloB + bo);
            }
#pragma unroll
            for (int mt = 0; mt < 2; mt++)
#pragma unroll
                for (int j = 0; j < 2; j++)
                    MMA_BF16(acc[mt][j], a[cur][mt], bh[cur][j], bh[cur][j + 2]);
            if (isHi) {
#pragma unroll
                for (int mt = 0; mt < 2; mt++)
#pragma unroll
                    for (int j = 0; j < 2; j++)
                        MMA_BF16(acc[mt][j], a[cur][mt], bl[cur][j], bl[cur][j + 2]);
            }
        }

        __syncthreads();
    }

    // ---------------- epilogue ----------------
    char* o2 = (char*)out2;
    int r0 = lane >> 2, cp = (lane & 3) * 2;
#pragma unroll
    for (int mt = 0; mt < 2; mt++) {
#pragma unroll
        for (int j = 0; j < 2; j++) {
            int n = n0 + warp_n + j * 8 + cp;
#pragma unroll
            for (int half = 0; half < 2; half++) {
                int m = m0 + warp_m + mt * 16 + r0 + half * 8;
                float v0 = acc[mt][j][half * 2 + 0];
                float v1 = acc[mt][j][half * 2 + 1];
                v0 = silu(v0);
                v1 = silu(v1);
                if (skip) {
                    float2 sk = *reinterpret_cast<const float2*>(skip + (size_t)m * 256 + n);
                    v0 += sk.x; v1 += sk.y;
                }
                if (outf) {
                    float2 o; o.x = v0; o.y = v1;
                    *reinterpret_cast<float2*>(outf + (size_t)m * 256 + n) = o;
                }
                if (out2) {
                    __nv_bfloat16 h0 = __float2bfloat16(v0);
                    __nv_bfloat16 h1 = __float2bfloat16(v1);
                    __nv_bfloat162 hh; hh.x = h0; hh.y = h1;
                    __nv_bfloat162 ll;
                    ll.x = __float2bfloat16(v0 - __bfloat162float(h0));
                    ll.y = __float2bfloat16(v1 - __bfloat162float(h1));
                    uint32_t loc = SWZ((uint32_t)(m * 128 + (n & 63) * 2));
                    *reinterpret_cast<__nv_bfloat162*>(
                        o2 + (size_t)(n >> 6) * ASLAB + loc) = hh;
                    *reinterpret_cast<__nv_bfloat162*>(
                        o2 + (size_t)(4 + (n >> 6)) * ASLAB + loc) = ll;
                }
            }
        }
    }
}

// ---------------- hi/lo conversion of h (slabbed, swizzled) ----------------
__global__ void conv_h_kernel(const float* __restrict__ h) {
    int idx = blockIdx.x * 256 + threadIdx.x;
    int m = idx >> 8, e = idx & 255;
    float v = h[idx];
    __nv_bfloat16 hi = __float2bfloat16(v);
    __nv_bfloat16 lo = __float2bfloat16(v - __bfloat162float(hi));
    uint32_t loc = SWZ((uint32_t)(m * 128 + (e & 63) * 2));
    char* base = (char*)g_x2a;
    *reinterpret_cast<__nv_bfloat16*>(base + (size_t)(e >> 6) * ASLAB + loc) = hi;
    *reinterpret_cast<__nv_bfloat16*>(base + (size_t)(4 + (e >> 6)) * ASLAB + loc) = lo;
}

// ---------------- weight conversion (slabbed, swizzled) ----------------
__global__ void conv_w_kernel(const float* __restrict__ Wpre,
                              const float* __restrict__ W0,
                              const float* __restrict__ Wres) {
    int g = blockIdx.y;
    int i = blockIdx.x * 256 + threadIdx.x;  // 0..65535
    int n = i >> 8, k = i & 255;
    const float* src = (g < 2) ? (Wpre + (size_t)g * 65536)
                     : (g == 2) ? W0
                     : (Wres + (size_t)(g - 3) * 65536);
    float v = src[i];
    __nv_bfloat16 hi = __float2bfloat16(v);
    __nv_bfloat16 lo = __float2bfloat16(v - __bfloat162float(hi));
    uint32_t loc = SWZ((uint32_t)((n & 63) * 128 + (k & 63) * 2));
    char* base = (char*)g_wc + (size_t)g * 262144 + (size_t)(n >> 6) * W_PB;
    *reinterpret_cast<__nv_bfloat16*>(base + (size_t)(k >> 6) * 8192 + loc) = hi;
    *reinterpret_cast<__nv_bfloat16*>(base + (size_t)(4 + (k >> 6)) * 8192 + loc) = lo;
}

// ---------------- segment offsets from sorted batch_seg ----------------
__global__ void seg_offsets_kernel(const int* __restrict__ seg) {
    int n = blockIdx.x * blockDim.x + threadIdx.x;
    if (n >= NN) return;
    int s = seg[n];
    if (n == 0) {
        for (int b = 0; b <= s; b++) g_off[b] = 0;
    } else {
        int p = seg[n - 1];
        for (int b = p + 1; b <= s; b++) g_off[b] = n;
    }
    if (n == NN - 1) {
        for (int b = s + 1; b <= BB; b++) g_off[b] = NN;
    }
}

// ---------------- dot products + cos/sin ----------------
__global__ void dot_kernel(const float* __restrict__ x,
                           const float* __restrict__ kvec,
                           const int* __restrict__ seg,
                           float* __restrict__ dot_out) {
    int n = blockIdx.x;
    int kk = threadIdx.x;  // 128
    int b = seg[n];
    float x0 = x[n * 3 + 0], x1 = x[n * 3 + 1], x2 = x[n * 3 + 2];
    const float* kr = kvec + ((size_t)b * KK + kk) * 3;
    float d = kr[0] * x0 + kr[1] * x1 + kr[2] * x2;
    dot_out[n * KK + kk] = d;
    float cv, sv;
    sincosf(d, &sv, &cv);
    g_c[n * KK + kk] = cv;
    g_s[n * KK + kk] = sv;
}

// ---------------- low-rank k-filter ----------------
__global__ void kf_kernel(const float* __restrict__ Wup,
                          const float* __restrict__ Wdn) {
    int e = threadIdx.x;
    int k = blockIdx.x;
    float a = 0.f;
#pragma unroll
    for (int d = 0; d < DD; d++) a += Wup[e * DD + d] * Wdn[d * KK + k];
    g_kf[k * EE + e] = a;
}

// ---------------- structure factors (kfilter folded in) ----------------
__global__ void __launch_bounds__(256, 4) sf_kernel() {
    int b  = blockIdx.z;
    int k0 = blockIdx.y * 32;
    int e0 = blockIdx.x * 32;
    int t = threadIdx.x;
    int e4 = t & 7;
    int ky = t >> 3;
    __shared__ float csh[32][32], ssh[32][32], hsh[32][32];
    int st = g_off[b], en = g_off[b + 1];
    float aR[4] = {0.f, 0.f, 0.f, 0.f};
    float aI[4] = {0.f, 0.f, 0.f, 0.f};
    for (int n0 = st; n0 < en; n0 += 32) {
#pragma unroll
        for (int l = 0; l < 4; l++) {
            int idx = t + 256 * l;
            int r = idx >> 5, c = idx & 31;
            int n = n0 + r;
            bool v = (n < en);
            csh[r][c] = v ? g_c[n * KK + k0 + c] : 0.f;
            ssh[r][c] = v ? g_s[n * KK + k0 + c] : 0.f;
            hsh[r][c] = v ? g_hres[(size_t)n * EE + e0 + c] : 0.f;
        }
        __syncthreads();
#pragma unroll
        for (int nn = 0; nn < 32; nn++) {
            float4 hv = *reinterpret_cast<float4*>(&hsh[nn][e4 * 4]);
            float cv = csh[nn][ky];
            float sv = ssh[nn][ky];
            aR[0] += cv * hv.x; aR[1] += cv * hv.y; aR[2] += cv * hv.z; aR[3] += cv * hv.w;
            aI[0] += sv * hv.x; aI[1] += sv * hv.y; aI[2] += sv * hv.z; aI[3] += sv * hv.w;
        }
        __syncthreads();
    }
    float4 f = *reinterpret_cast<float4*>(&g_kf[(k0 + ky) * EE + e0 + e4 * 4]);
    size_t idx = ((size_t)b * KK + k0 + ky) * EE + e0 + e4 * 4;
    float4 oR, oI;
    oR.x = aR[0] * f.x; oR.y = aR[1] * f.y; oR.z = aR[2] * f.z; oR.w = aR[3] * f.w;
    oI.x = aI[0] * f.x; oI.y = aI[1] * f.y; oI.z = aI[2] * f.z; oI.w = aI[3] * f.w;
    *reinterpret_cast<float4*>(&g_sfr[idx]) = oR;
    *reinterpret_cast<float4*>(&g_sfi[idx]) = oI;
}

// ---------------- back-projection; writes hi/lo bf16 (slabbed) --------------
__global__ void __launch_bounds__(256, 4) hupd_kernel(const int* __restrict__ seg) {
    int n0 = blockIdx.y * 32;
    int e0 = blockIdx.x * 32;
    int t = threadIdx.x;
    int e4 = t & 7;
    int ny = t >> 3;
    int n = n0 + ny;
    int b = seg[n];
    __shared__ float csh[32][32], ssh[32][32];
    float acc[4] = {0.f, 0.f, 0.f, 0.f};
    for (int k0c = 0; k0c < KK; k0c += 32) {
#pragma unroll
        for (int l = 0; l < 4; l++) {
            int idx = t + 256 * l;
            int r = idx >> 5, c = idx & 31;
            csh[r][c] = g_c[(n0 + r) * KK + k0c + c];
            ssh[r][c] = g_s[(n0 + r) * KK + k0c + c];
        }
        __syncthreads();
        const float* baseR = g_sfr + ((size_t)b * KK + k0c) * EE + e0 + e4 * 4;
        const float* baseI = g_sfi + ((size_t)b * KK + k0c) * EE + e0 + e4 * 4;
#pragma unroll
        for (int kk = 0; kk < 32; kk++) {
            float cv = csh[ny][kk];
            float sv = ssh[ny][kk];
            float4 pr = *reinterpret_cast<const float4*>(baseR + (size_t)kk * EE);
            float4 pi = *reinterpret_cast<const float4*>(baseI + (size_t)kk * EE);
            acc[0] += cv * pr.x + sv * pi.x;
            acc[1] += cv * pr.y + sv * pi.y;
            acc[2] += cv * pr.z + sv * pi.z;
            acc[3] += cv * pr.w + sv * pi.w;
        }
        __syncthreads();
    }
    __nv_bfloat16 hi[4], lo[4];
#pragma unroll
    for (int q = 0; q < 4; q++) {
        float v = 0.01f * acc[q];
        hi[q] = __float2bfloat16(v);
        lo[q] = __float2bfloat16(v - __bfloat162float(hi[q]));
    }
    int e = e0 + e4 * 4;
    uint32_t loc = SWZ((uint32_t)(n * 128 + (e & 63) * 2));
    char* base = (char*)g_x2a;
    *reinterpret_cast<uint2*>(base + (size_t)(e >> 6) * ASLAB + loc) =
        *reinterpret_cast<uint2*>(hi);
    *reinterpret_cast<uint2*>(base + (size_t)(4 + (e >> 6)) * ASLAB + loc) =
        *reinterpret_cast<uint2*>(lo);
}

// ---------------- launch ----------------
extern "C" void kernel_launch(void* const* d_in, const int* in_sizes, int n_in,
                              void* d_out, int out_size) {
    const float *h = nullptr, *x = nullptr, *kv = nullptr;
    const float *Wpre = nullptr, *Wdn = nullptr, *Wup = nullptr;
    const float *W0 = nullptr, *Wres = nullptr;
    const int* seg = nullptr;

    for (int i = 0; i < n_in; i++) {
        switch (in_sizes[i]) {
            case NN * EE:           h    = (const float*)d_in[i]; break;
            case NN * 3:            x    = (const float*)d_in[i]; break;
            case BB * KK * 3:       kv   = (const float*)d_in[i]; break;
            case NN:                seg  = (const int*)d_in[i];   break;
            case 2 * EE * EE:       Wpre = (const float*)d_in[i]; break;
            case DD * KK:           Wdn  = (const float*)d_in[i]; break;
            case EE * DD:           Wup  = (const float*)d_in[i]; break;
            case EE * EE:           W0   = (const float*)d_in[i]; break;
            case 3 * 2 * EE * EE:   Wres = (const float*)d_in[i]; break;
            default: break;
        }
    }

    float* out = (float*)d_out;
    float* out_hu  = out;            // (NN, EE)
    float* out_dot = out + NN * EE;  // (NN, KK)

    float *t0, *hres;
    __nv_bfloat16 *x2a, *x2b, *wc;
    cudaGetSymbolAddress((void**)&t0,   g_t0);
    cudaGetSymbolAddress((void**)&hres, g_hres);
    cudaGetSymbolAddress((void**)&x2a,  g_x2a);
    cudaGetSymbolAddress((void**)&x2b,  g_x2b);
    cudaGetSymbolAddress((void**)&wc,   g_wc);

    cudaFuncSetAttribute(gemm_mma_kernel,
                         cudaFuncAttributeMaxDynamicSharedMemorySize, GEMM_SMEM);
    dim3 ggrid(EE / 64, NN / 64);  // (4, 64) = 256 CTAs -> 2/SM

    // conversions
    conv_w_kernel<<<dim3(256, 9), 256>>>(Wpre, W0, Wres);
    conv_h_kernel<<<NN * EE / 256, 256>>>(h);

    // pre-residual: x2b = silu(h@W0'), hres = h + silu(x2b@W1')
    gemm_mma_kernel<<<ggrid, 256, GEMM_SMEM>>>(x2a, wc + 0 * 131072, nullptr, nullptr, x2b);
    gemm_mma_kernel<<<ggrid, 256, GEMM_SMEM>>>(x2b, wc + 1 * 131072, h, hres, nullptr);

    // Ewald geometry path
    seg_offsets_kernel<<<(NN + 255) / 256, 256>>>(seg);
    dot_kernel<<<NN, KK>>>(x, kv, seg, out_dot);
    kf_kernel<<<KK, EE>>>(Wup, Wdn);
    sf_kernel<<<dim3(EE / 32, KK / 32, BB), 256>>>();
    hupd_kernel<<<dim3(EE / 32, NN / 32), 256>>>(seg);  // -> g_x2a (slabbed hi/lo)

    // update MLP: t0 = silu(hu @ W0^T)
    gemm_mma_kernel<<<ggrid, 256, GEMM_SMEM>>>(x2a, wc + 2 * 131072, nullptr, t0, x2b);

    // 3 residual blocks
    for (int i = 0; i < 3; i++) {
        const __nv_bfloat16* wa = wc + (size_t)(3 + 2 * i) * 131072;
        const __nv_bfloat16* wb = wc + (size_t)(4 + 2 * i) * 131072;
        gemm_mma_kernel<<<ggrid, 256, GEMM_SMEM>>>(x2b, wa, nullptr, nullptr, x2a);
        float* dstf = (i == 2) ? out_hu : t0;
        __nv_bfloat16* dst2 = (i == 2) ? nullptr : x2b;
        gemm_mma_kernel<<<ggrid, 256, GEMM_SMEM>>>(x2a, wb, t0, dstf, dst2);
    }
}